// round 6
// baseline (speedup 1.0000x reference)
#include <cuda_runtime.h>
#include <cuda_bf16.h>
#include <cstdint>

#define Bn 16
#define Cn 512
#define Hn 64
#define Wn 64
#define Rn 64
#define A_LD 72   // padded bf16 row stride (144B = 9x16B, ldmatrix-friendly)

// Scratch (device globals; no allocation allowed)
__device__ float g_sumC[Bn*Cn];
__device__ float g_partW[Bn*Cn*Wn];
__device__ float g_partH[Bn*Cn*Hn];
__device__ __align__(16) __nv_bfloat16 g_cAb[Bn*Cn*A_LD];  // A[b][c][r] bf16
__device__ float g_wout[Bn*Rn*Wn];  // [b][r][w]
__device__ float g_hout[Bn*Rn*Hn];  // [b][r][h]
__device__ __align__(16) __nv_bfloat16 g_cp[(size_t)Bn*Cn*Hn*Wn];  // logits bf16
__device__ float g_psum[4*Bn*Hn*Wn];  // partial exp-sums [cT][b][h][w]

__device__ __forceinline__ unsigned s2u(const void* p) {
    return (unsigned)__cvta_generic_to_shared(p);
}

// ---------------------------------------------------------------------------
// K1: per-(b,c) plane reductions
// ---------------------------------------------------------------------------
__global__ __launch_bounds__(256) void k_reduce(const float* __restrict__ x) {
    int plane = blockIdx.x;
    const float4* x4 = (const float4*)(x + (size_t)plane * 4096);
    int tid = threadIdx.x;

    __shared__ float4 s4[256];
    __shared__ float  sh[256][4];

    float4 wacc = make_float4(0.f, 0.f, 0.f, 0.f);
    float hacc[4];
#pragma unroll
    for (int k = 0; k < 4; k++) {
        float4 f = x4[tid + 256 * k];
        wacc.x += f.x; wacc.y += f.y; wacc.z += f.z; wacc.w += f.w;
        hacc[k] = f.x + f.y + f.z + f.w;
    }
    s4[tid] = wacc;
    sh[tid][0] = hacc[0]; sh[tid][1] = hacc[1];
    sh[tid][2] = hacc[2]; sh[tid][3] = hacc[3];
    __syncthreads();

    if (tid < 16) {
        float4 t = s4[tid];
#pragma unroll
        for (int j = 1; j < 16; j++) {
            float4 u = s4[tid + 16 * j];
            t.x += u.x; t.y += u.y; t.z += u.z; t.w += u.w;
        }
        ((float4*)g_partW)[plane * 16 + tid] = t;
        s4[tid] = t;
    }
    if (tid >= 64 && tid < 128) {
        int h = tid - 64;
        int base = (h & 15) * 16;
        int k = h >> 4;
        float s = 0.f;
#pragma unroll
        for (int j = 0; j < 16; j++) s += sh[base + j][k];
        g_partH[plane * 64 + h] = s;
    }
    __syncthreads();
    if (tid == 0) {
        float tot = 0.f;
#pragma unroll
        for (int j = 0; j < 16; j++) {
            float4 u = s4[j];
            tot += u.x + u.y + u.z + u.w;
        }
        g_sumC[plane] = tot;
    }
}

// ---------------------------------------------------------------------------
// K2: finish gap means, 3-tap convs + PReLU
// ---------------------------------------------------------------------------
__global__ __launch_bounds__(256) void k_branches(
    const float* __restrict__ w_c, const float* __restrict__ a_c,
    const float* __restrict__ w_w, const float* __restrict__ a_w,
    const float* __restrict__ w_h, const float* __restrict__ a_h) {
    int b = blockIdx.x, tid = threadIdx.x;
    __shared__ float gc[Cn + 2];
    __shared__ float gw[Wn + 2];
    __shared__ float gh[Hn + 2];
    __shared__ float red[4][64];

    for (int i = tid; i < Cn; i += 256)
        gc[i + 1] = g_sumC[b * Cn + i] * (1.f / 4096.f);
    if (tid == 0) {
        gc[0] = 0.f; gc[Cn + 1] = 0.f;
        gw[0] = 0.f; gw[Wn + 1] = 0.f;
        gh[0] = 0.f; gh[Hn + 1] = 0.f;
    }
    {
        int q = tid >> 6, w = tid & 63;
        float s = 0.f;
        const float* p = g_partW + ((size_t)(b * Cn + q * 128)) * 64 + w;
#pragma unroll 4
        for (int c = 0; c < 128; c++) s += p[c * 64];
        red[q][w] = s;
    }
    __syncthreads();
    if (tid < 64)
        gw[tid + 1] = (red[0][tid] + red[1][tid] + red[2][tid] + red[3][tid]) * (1.f / 32768.f);
    __syncthreads();
    {
        int q = tid >> 6, hh = tid & 63;
        float s = 0.f;
        const float* p = g_partH + ((size_t)(b * Cn + q * 128)) * 64 + hh;
#pragma unroll 4
        for (int c = 0; c < 128; c++) s += p[c * 64];
        red[q][hh] = s;
    }
    __syncthreads();
    if (tid < 64)
        gh[tid + 1] = (red[0][tid] + red[1][tid] + red[2][tid] + red[3][tid]) * (1.f / 32768.f);
    __syncthreads();

    float acv = a_c[0], awv = a_w[0], ahv = a_h[0];
    for (int i = tid; i < Rn * Cn; i += 256) {
        int r = i >> 9, c = i & 511;
        float v = w_c[r * 3] * gc[c] + w_c[r * 3 + 1] * gc[c + 1] + w_c[r * 3 + 2] * gc[c + 2];
        v = (v >= 0.f) ? v : acv * v;
        g_cAb[((size_t)(b * Cn + c)) * A_LD + r] = __float2bfloat16(v);
    }
    for (int i = tid; i < Rn * Wn; i += 256) {
        int r = i >> 6, w = i & 63;
        float v = w_w[r * 3] * gw[w] + w_w[r * 3 + 1] * gw[w + 1] + w_w[r * 3 + 2] * gw[w + 2];
        g_wout[b * Rn * Wn + i] = (v >= 0.f) ? v : awv * v;
        float v2 = w_h[r * 3] * gh[w] + w_h[r * 3 + 1] * gh[w + 1] + w_h[r * 3 + 2] * gh[w + 2];
        g_hout[b * Rn * Hn + i] = (v2 >= 0.f) ? v2 : ahv * v2;
    }
}

// ---------------------------------------------------------------------------
// K3a: tiled MMA, block = (cT 128-c tile, h, b). Writes cp bf16 + partial
// column sums of exp(cp). No max pass: |cp| << 1 so exp can't overflow.
// ---------------------------------------------------------------------------
#define GE_A    0                 // bf16 [128][A_LD] = 18432
#define GE_S    18432             // bf16 [64][A_LD]  = 9216
#define GE_RED  27648             // f32 [8][64]      = 2048
#define GE_BYTES 29696

__global__ void __launch_bounds__(256) k_gemmE(int dummy) {
    extern __shared__ char sm[];
    int cT = blockIdx.x, h = blockIdx.y, b = blockIdx.z;
    int tid = threadIdx.x;
    int lane = tid & 31, wid = tid >> 5;

    // stage A tile (contiguous 18432B, 16B-aligned) + build S
    {
        const uint4* src = (const uint4*)(g_cAb + ((size_t)b * 512 + cT * 128) * A_LD);
        uint4* dst = (uint4*)(sm + GE_A);
        for (int i = tid; i < 1152; i += 256) dst[i] = src[i];
        const float* ho = g_hout + b * Rn * Hn;
        const float* wo = g_wout + b * Rn * Wn;
        __nv_bfloat16* S = (__nv_bfloat16*)(sm + GE_S);
        for (int i = tid; i < 4096; i += 256) {
            int r = i >> 6, w = i & 63;
            S[r * A_LD + w] = __float2bfloat16(ho[r * 64 + h] * wo[r * 64 + w]);
        }
    }
    __syncthreads();

    // MMA: warp owns 16 c rows x 64 w
    float acc[8][4];
#pragma unroll
    for (int t = 0; t < 8; t++)
#pragma unroll
        for (int r = 0; r < 4; r++) acc[t][r] = 0.f;

    {
        unsigned aBase = s2u(sm + GE_A);
        unsigned sBase = s2u(sm + GE_S);
        int cb = wid * 16;
        int aRow = lane & 15;
        unsigned aColOff = (unsigned)(lane >> 4) * 16u;
        int bRowOff = (lane & 7) + ((lane & 8) ? 8 : 0);
        int bColOff = (lane & 16) ? 8 : 0;
#pragma unroll
        for (int ks = 0; ks < 4; ks++) {
            int k0 = ks * 16;
            unsigned a0, a1, a2, a3;
            unsigned ad = aBase + (unsigned)((cb + aRow) * A_LD + k0) * 2u + aColOff;
            asm volatile("ldmatrix.sync.aligned.m8n8.x4.shared.b16 {%0,%1,%2,%3}, [%4];\n"
                         : "=r"(a0), "=r"(a1), "=r"(a2), "=r"(a3) : "r"(ad));
#pragma unroll
            for (int nb = 0; nb < 4; nb++) {
                unsigned bd = sBase + (unsigned)((k0 + bRowOff) * A_LD + nb * 16 + bColOff) * 2u;
                unsigned bq0, bq1, bq2, bq3;
                asm volatile("ldmatrix.sync.aligned.m8n8.x4.trans.shared.b16 {%0,%1,%2,%3}, [%4];\n"
                             : "=r"(bq0), "=r"(bq1), "=r"(bq2), "=r"(bq3) : "r"(bd));
                asm volatile(
                    "mma.sync.aligned.m16n8k16.row.col.f32.bf16.bf16.f32 "
                    "{%0,%1,%2,%3},{%4,%5,%6,%7},{%8,%9},{%0,%1,%2,%3};\n"
                    : "+f"(acc[2 * nb][0]), "+f"(acc[2 * nb][1]),
                      "+f"(acc[2 * nb][2]), "+f"(acc[2 * nb][3])
                    : "r"(a0), "r"(a1), "r"(a2), "r"(a3), "r"(bq0), "r"(bq1));
                asm volatile(
                    "mma.sync.aligned.m16n8k16.row.col.f32.bf16.bf16.f32 "
                    "{%0,%1,%2,%3},{%4,%5,%6,%7},{%8,%9},{%0,%1,%2,%3};\n"
                    : "+f"(acc[2 * nb + 1][0]), "+f"(acc[2 * nb + 1][1]),
                      "+f"(acc[2 * nb + 1][2]), "+f"(acc[2 * nb + 1][3])
                    : "r"(a0), "r"(a1), "r"(a2), "r"(a3), "r"(bq2), "r"(bq3));
            }
        }
    }

    // write cp (bf16) directly from accumulators
    {
        int c_lo = cT * 128 + wid * 16 + (lane >> 2);
#pragma unroll
        for (int t = 0; t < 8; t++) {
            int w = t * 8 + (lane & 3) * 2;
            __nv_bfloat162* p0 = (__nv_bfloat162*)(g_cp +
                ((size_t)(b * 512 + c_lo) * 64 + h) * 64 + w);
            *p0 = __floats2bfloat162_rn(acc[t][0], acc[t][1]);
            __nv_bfloat162* p1 = (__nv_bfloat162*)(g_cp +
                ((size_t)(b * 512 + c_lo + 8) * 64 + h) * 64 + w);
            *p1 = __floats2bfloat162_rn(acc[t][2], acc[t][3]);
        }
    }

    // partial column sums of exp(cp) over this 128-c tile
    float* wred = (float*)(sm + GE_RED);
#pragma unroll
    for (int t = 0; t < 8; t++) {
        float sA = __expf(acc[t][0]) + __expf(acc[t][2]);
        float sB = __expf(acc[t][1]) + __expf(acc[t][3]);
        sA += __shfl_xor_sync(0xffffffffu, sA, 4);
        sB += __shfl_xor_sync(0xffffffffu, sB, 4);
        sA += __shfl_xor_sync(0xffffffffu, sA, 8);
        sB += __shfl_xor_sync(0xffffffffu, sB, 8);
        sA += __shfl_xor_sync(0xffffffffu, sA, 16);
        sB += __shfl_xor_sync(0xffffffffu, sB, 16);
        if (lane < 4) {
            wred[wid * 64 + t * 8 + (lane & 3) * 2]     = sA;
            wred[wid * 64 + t * 8 + (lane & 3) * 2 + 1] = sB;
        }
    }
    __syncthreads();
    if (tid < 64) {
        float s = wred[tid];
#pragma unroll
        for (int k = 1; k < 8; k++) s += wred[k * 64 + tid];
        g_psum[(((size_t)cT * 16 + b) * 64 + h) * 64 + tid] = s;
    }
}

// ---------------------------------------------------------------------------
// K3b: stencil conv3d + softmax-normalize + residual.
// Block = (16-c tile, 8-h tile, b), 512 thr, 2 c per thread, 2 CTAs/SM.
// ---------------------------------------------------------------------------
#define CV_XT_F   (18 * 10 * 64)          // floats
#define CV_BYTES  (CV_XT_F * 4 + 128)     // + w3 shared

__global__ void __launch_bounds__(512, 2) k_conv(
    const float* __restrict__ x, const float* __restrict__ w3d,
    float* __restrict__ out) {
    extern __shared__ float xt[];          // [18 c][10 h][64 w]
    float* w3s = xt + CV_XT_F;             // [27]
    int h0 = blockIdx.x * 8;
    int c0 = blockIdx.y * 16;
    int b  = blockIdx.z;
    int tid = threadIdx.x;

    if (tid < 27) w3s[tid] = w3d[tid];

    // load halo tile (18c x 10h x 64w) via cp.async with zero-fill
    {
        unsigned dstb = s2u(xt);
        const float4* x4 = (const float4*)x;
        for (int i = tid; i < 2880; i += 512) {
            int w4 = i & 15, rest = i >> 4;
            int hi = rest % 10, ci = rest / 10;
            int cg = c0 - 1 + ci, hg = h0 - 1 + hi;
            bool ok = ((unsigned)cg < 512u) && ((unsigned)hg < 64u);
            const float4* src = ok ? (x4 + (((size_t)(b * 512 + cg) * 64 + hg) * 16 + w4)) : x4;
            int sz = ok ? 16 : 0;
            asm volatile("cp.async.cg.shared.global [%0], [%1], 16, %2;\n"
                         :: "r"(dstb + (unsigned)i * 16), "l"((const void*)src), "r"(sz));
        }
        asm volatile("cp.async.commit_group;\n" ::);
        asm volatile("cp.async.wait_group 0;\n" ::);
    }
    __syncthreads();

    int wg = tid & 7, hq = (tid >> 3) & 7, cq = tid >> 6;  // cq 0..7, 2c each
    int h = h0 + hq;

    float res[2][8];
#pragma unroll
    for (int i = 0; i < 2; i++)
#pragma unroll
        for (int j = 0; j < 8; j++) res[i][j] = 0.f;

    // input-stationary: rows j = cq*2 + ii (ii 0..3), each feeds cc = ii - dc
#pragma unroll
    for (int ii = 0; ii < 4; ii++) {
#pragma unroll
        for (int dhi = 0; dhi < 3; dhi++) {
            const float* row = xt + ((cq * 2 + ii) * 10 + (hq + dhi)) * 64 + wg * 8;
            float4 m0 = *(const float4*)row;
            float4 m1 = *(const float4*)(row + 4);
            float left  = (wg == 0) ? 0.f : row[-1];
            float right = (wg == 7) ? 0.f : row[8];
            float v[10] = {left, m0.x, m0.y, m0.z, m0.w,
                           m1.x, m1.y, m1.z, m1.w, right};
#pragma unroll
            for (int dc = 0; dc < 3; dc++) {
                int cc = ii - dc;
                if (cc < 0 || cc > 1) continue;
                int t = (dc * 3 + dhi) * 3;
                float k0 = w3s[t], k1 = w3s[t + 1], k2 = w3s[t + 2];
#pragma unroll
                for (int j = 0; j < 8; j++)
                    res[cc][j] += k0 * v[j] + k1 * v[j + 1] + k2 * v[j + 2];
            }
        }
    }

    // softmax denominators for this (h, 8w): sum 4 cT partials
    float inv[8];
    {
        float4 s0 = make_float4(0.f, 0.f, 0.f, 0.f), s1 = s0;
#pragma unroll
        for (int ct = 0; ct < 4; ct++) {
            const float4* pp = (const float4*)(g_psum +
                (((size_t)ct * 16 + b) * 64 + h) * 64 + wg * 8);
            float4 p0 = pp[0], p1 = pp[1];
            s0.x += p0.x; s0.y += p0.y; s0.z += p0.z; s0.w += p0.w;
            s1.x += p1.x; s1.y += p1.y; s1.z += p1.z; s1.w += p1.w;
        }
        inv[0] = 1.f / s0.x; inv[1] = 1.f / s0.y; inv[2] = 1.f / s0.z; inv[3] = 1.f / s0.w;
        inv[4] = 1.f / s1.x; inv[5] = 1.f / s1.y; inv[6] = 1.f / s1.z; inv[7] = 1.f / s1.w;
    }

    // epilogue: o = res * exp(cp)*inv + x
#pragma unroll
    for (int cc = 0; cc < 2; cc++) {
        int c = c0 + cq * 2 + cc;
        const float* ctr = xt + ((cq * 2 + cc + 1) * 10 + (hq + 1)) * 64 + wg * 8;
        float4 xi0 = *(const float4*)ctr;
        float4 xi1 = *(const float4*)(ctr + 4);
        uint4 cv = *(const uint4*)(g_cp + ((size_t)(b * 512 + c) * 64 + h) * 64 + wg * 8);
        const __nv_bfloat162* cpp = (const __nv_bfloat162*)&cv;
        float xin[8] = {xi0.x, xi0.y, xi0.z, xi0.w, xi1.x, xi1.y, xi1.z, xi1.w};
        float o[8];
#pragma unroll
        for (int j2 = 0; j2 < 4; j2++) {
            float2 cf = __bfloat1622float2(cpp[j2]);
            o[2 * j2]     = res[cc][2 * j2]     * (__expf(cf.x) * inv[2 * j2])     + xin[2 * j2];
            o[2 * j2 + 1] = res[cc][2 * j2 + 1] * (__expf(cf.y) * inv[2 * j2 + 1]) + xin[2 * j2 + 1];
        }
        float* op = out + (((size_t)(b * 512 + c) * 64 + h) * 64 + wg * 8);
        *(float4*)(op)     = make_float4(o[0], o[1], o[2], o[3]);
        *(float4*)(op + 4) = make_float4(o[4], o[5], o[6], o[7]);
    }
}

// ---------------------------------------------------------------------------
extern "C" void kernel_launch(void* const* d_in, const int* in_sizes, int n_in,
                              void* d_out, int out_size) {
    const float* x   = (const float*)d_in[0];
    const float* w_c = (const float*)d_in[1];
    const float* a_c = (const float*)d_in[2];
    const float* w_w = (const float*)d_in[3];
    const float* a_w = (const float*)d_in[4];
    const float* w_h = (const float*)d_in[5];
    const float* a_h = (const float*)d_in[6];
    const float* w3d = (const float*)d_in[7];
    float* out = (float*)d_out;

    cudaFuncSetAttribute(k_gemmE, cudaFuncAttributeMaxDynamicSharedMemorySize, GE_BYTES);
    cudaFuncSetAttribute(k_conv, cudaFuncAttributeMaxDynamicSharedMemorySize, CV_BYTES);

    k_reduce<<<Bn * Cn, 256>>>(x);
    k_branches<<<Bn, 256>>>(w_c, a_c, w_w, a_w, w_h, a_h);
    dim3 gridG(4, Hn, Bn);
    k_gemmE<<<gridG, 256, GE_BYTES>>>(0);
    dim3 gridC(8, 32, Bn);
    k_conv<<<gridC, 512, CV_BYTES>>>(x, w3d, out);
}

// round 7
// speedup vs baseline: 1.0310x; 1.0310x over previous
#include <cuda_runtime.h>
#include <cuda_bf16.h>
#include <cstdint>

#define Bn 16
#define Cn 512
#define Hn 64
#define Wn 64
#define Rn 64
#define A_LD 72   // padded bf16 row stride (144B = 9x16B, ldmatrix-friendly)

typedef unsigned long long ull;

// Scratch (device globals; no allocation allowed)
__device__ float g_sumC[Bn*Cn];
__device__ float g_partW[Bn*Cn*Wn];
__device__ float g_partH[Bn*Cn*Hn];
__device__ __align__(16) __nv_bfloat16 g_cAb[Bn*Cn*A_LD];  // A[b][c][r] bf16
__device__ float g_wout[Bn*Rn*Wn];  // [b][r][w]
__device__ float g_hout[Bn*Rn*Hn];  // [b][r][h]
__device__ __align__(16) __nv_bfloat16 g_cp[(size_t)Bn*Cn*Hn*Wn];  // logits bf16
__device__ float g_psum[4*Bn*Hn*Wn];  // partial exp-sums [cT][b][h][w]

__device__ __forceinline__ unsigned s2u(const void* p) {
    return (unsigned)__cvta_generic_to_shared(p);
}

#define FMA2(d, a, bb) asm("fma.rn.f32x2 %0, %1, %2, %3;" : "=l"(d) : "l"(a), "l"(bb), "l"(d))
#define PK2(d, lo, hi) asm("mov.b64 %0, {%1, %2};" : "=l"(d) : "f"(lo), "f"(hi))
#define UPK2(lo, hi, v) asm("mov.b64 {%0, %1}, %2;" : "=f"(lo), "=f"(hi) : "l"(v))

// ---------------------------------------------------------------------------
// K1: per-(b,c) plane reductions
// ---------------------------------------------------------------------------
__global__ __launch_bounds__(256) void k_reduce(const float* __restrict__ x) {
    int plane = blockIdx.x;
    const float4* x4 = (const float4*)(x + (size_t)plane * 4096);
    int tid = threadIdx.x;

    __shared__ float4 s4[256];
    __shared__ float  sh[256][4];

    float4 wacc = make_float4(0.f, 0.f, 0.f, 0.f);
    float hacc[4];
#pragma unroll
    for (int k = 0; k < 4; k++) {
        float4 f = x4[tid + 256 * k];
        wacc.x += f.x; wacc.y += f.y; wacc.z += f.z; wacc.w += f.w;
        hacc[k] = f.x + f.y + f.z + f.w;
    }
    s4[tid] = wacc;
    sh[tid][0] = hacc[0]; sh[tid][1] = hacc[1];
    sh[tid][2] = hacc[2]; sh[tid][3] = hacc[3];
    __syncthreads();

    if (tid < 16) {
        float4 t = s4[tid];
#pragma unroll
        for (int j = 1; j < 16; j++) {
            float4 u = s4[tid + 16 * j];
            t.x += u.x; t.y += u.y; t.z += u.z; t.w += u.w;
        }
        ((float4*)g_partW)[plane * 16 + tid] = t;
        s4[tid] = t;
    }
    if (tid >= 64 && tid < 128) {
        int h = tid - 64;
        int base = (h & 15) * 16;
        int k = h >> 4;
        float s = 0.f;
#pragma unroll
        for (int j = 0; j < 16; j++) s += sh[base + j][k];
        g_partH[plane * 64 + h] = s;
    }
    __syncthreads();
    if (tid == 0) {
        float tot = 0.f;
#pragma unroll
        for (int j = 0; j < 16; j++) {
            float4 u = s4[j];
            tot += u.x + u.y + u.z + u.w;
        }
        g_sumC[plane] = tot;
    }
}

// ---------------------------------------------------------------------------
// K2: finish gap means, 3-tap convs + PReLU
// ---------------------------------------------------------------------------
__global__ __launch_bounds__(256) void k_branches(
    const float* __restrict__ w_c, const float* __restrict__ a_c,
    const float* __restrict__ w_w, const float* __restrict__ a_w,
    const float* __restrict__ w_h, const float* __restrict__ a_h) {
    int b = blockIdx.x, tid = threadIdx.x;
    __shared__ float gc[Cn + 2];
    __shared__ float gw[Wn + 2];
    __shared__ float gh[Hn + 2];
    __shared__ float red[4][64];

    for (int i = tid; i < Cn; i += 256)
        gc[i + 1] = g_sumC[b * Cn + i] * (1.f / 4096.f);
    if (tid == 0) {
        gc[0] = 0.f; gc[Cn + 1] = 0.f;
        gw[0] = 0.f; gw[Wn + 1] = 0.f;
        gh[0] = 0.f; gh[Hn + 1] = 0.f;
    }
    {
        int q = tid >> 6, w = tid & 63;
        float s = 0.f;
        const float* p = g_partW + ((size_t)(b * Cn + q * 128)) * 64 + w;
#pragma unroll 4
        for (int c = 0; c < 128; c++) s += p[c * 64];
        red[q][w] = s;
    }
    __syncthreads();
    if (tid < 64)
        gw[tid + 1] = (red[0][tid] + red[1][tid] + red[2][tid] + red[3][tid]) * (1.f / 32768.f);
    __syncthreads();
    {
        int q = tid >> 6, hh = tid & 63;
        float s = 0.f;
        const float* p = g_partH + ((size_t)(b * Cn + q * 128)) * 64 + hh;
#pragma unroll 4
        for (int c = 0; c < 128; c++) s += p[c * 64];
        red[q][hh] = s;
    }
    __syncthreads();
    if (tid < 64)
        gh[tid + 1] = (red[0][tid] + red[1][tid] + red[2][tid] + red[3][tid]) * (1.f / 32768.f);
    __syncthreads();

    float acv = a_c[0], awv = a_w[0], ahv = a_h[0];
    for (int i = tid; i < Rn * Cn; i += 256) {
        int r = i >> 9, c = i & 511;
        float v = w_c[r * 3] * gc[c] + w_c[r * 3 + 1] * gc[c + 1] + w_c[r * 3 + 2] * gc[c + 2];
        v = (v >= 0.f) ? v : acv * v;
        g_cAb[((size_t)(b * Cn + c)) * A_LD + r] = __float2bfloat16(v);
    }
    for (int i = tid; i < Rn * Wn; i += 256) {
        int r = i >> 6, w = i & 63;
        float v = w_w[r * 3] * gw[w] + w_w[r * 3 + 1] * gw[w + 1] + w_w[r * 3 + 2] * gw[w + 2];
        g_wout[b * Rn * Wn + i] = (v >= 0.f) ? v : awv * v;
        float v2 = w_h[r * 3] * gh[w] + w_h[r * 3 + 1] * gh[w + 1] + w_h[r * 3 + 2] * gh[w + 2];
        g_hout[b * Rn * Hn + i] = (v2 >= 0.f) ? v2 : ahv * v2;
    }
}

// ---------------------------------------------------------------------------
// K3a: tiled MMA, block = (cT 128-c tile, h, b). cp staged in smem ->
// coalesced bf16 stores; partial exp-sums to g_psum.
// ---------------------------------------------------------------------------
#define GE_A    0                 // bf16 [128][A_LD] = 18432 (A, then cp tile)
#define GE_S    18432             // bf16 [64][A_LD]  = 9216
#define GE_RED  27648             // f32 [8][64]      = 2048
#define GE_BYTES 29696

__global__ void __launch_bounds__(256) k_gemmE(int dummy) {
    extern __shared__ char sm[];
    int cT = blockIdx.x, h = blockIdx.y, b = blockIdx.z;
    int tid = threadIdx.x;
    int lane = tid & 31, wid = tid >> 5;

    // stage A tile + build S
    {
        const uint4* src = (const uint4*)(g_cAb + ((size_t)b * 512 + cT * 128) * A_LD);
        uint4* dst = (uint4*)(sm + GE_A);
        for (int i = tid; i < 1152; i += 256) dst[i] = src[i];
        const float* ho = g_hout + b * Rn * Hn;
        const float* wo = g_wout + b * Rn * Wn;
        __nv_bfloat16* S = (__nv_bfloat16*)(sm + GE_S);
        for (int i = tid; i < 4096; i += 256) {
            int r = i >> 6, w = i & 63;
            S[r * A_LD + w] = __float2bfloat16(ho[r * 64 + h] * wo[r * 64 + w]);
        }
    }
    __syncthreads();

    // MMA: warp owns 16 c rows x 64 w
    float acc[8][4];
#pragma unroll
    for (int t = 0; t < 8; t++)
#pragma unroll
        for (int r = 0; r < 4; r++) acc[t][r] = 0.f;

    {
        unsigned aBase = s2u(sm + GE_A);
        unsigned sBase = s2u(sm + GE_S);
        int cb = wid * 16;
        int aRow = lane & 15;
        unsigned aColOff = (unsigned)(lane >> 4) * 16u;
        int bRowOff = (lane & 7) + ((lane & 8) ? 8 : 0);
        int bColOff = (lane & 16) ? 8 : 0;
#pragma unroll
        for (int ks = 0; ks < 4; ks++) {
            int k0 = ks * 16;
            unsigned a0, a1, a2, a3;
            unsigned ad = aBase + (unsigned)((cb + aRow) * A_LD + k0) * 2u + aColOff;
            asm volatile("ldmatrix.sync.aligned.m8n8.x4.shared.b16 {%0,%1,%2,%3}, [%4];\n"
                         : "=r"(a0), "=r"(a1), "=r"(a2), "=r"(a3) : "r"(ad));
#pragma unroll
            for (int nb = 0; nb < 4; nb++) {
                unsigned bd = sBase + (unsigned)((k0 + bRowOff) * A_LD + nb * 16 + bColOff) * 2u;
                unsigned bq0, bq1, bq2, bq3;
                asm volatile("ldmatrix.sync.aligned.m8n8.x4.trans.shared.b16 {%0,%1,%2,%3}, [%4];\n"
                             : "=r"(bq0), "=r"(bq1), "=r"(bq2), "=r"(bq3) : "r"(bd));
                asm volatile(
                    "mma.sync.aligned.m16n8k16.row.col.f32.bf16.bf16.f32 "
                    "{%0,%1,%2,%3},{%4,%5,%6,%7},{%8,%9},{%0,%1,%2,%3};\n"
                    : "+f"(acc[2 * nb][0]), "+f"(acc[2 * nb][1]),
                      "+f"(acc[2 * nb][2]), "+f"(acc[2 * nb][3])
                    : "r"(a0), "r"(a1), "r"(a2), "r"(a3), "r"(bq0), "r"(bq1));
                asm volatile(
                    "mma.sync.aligned.m16n8k16.row.col.f32.bf16.bf16.f32 "
                    "{%0,%1,%2,%3},{%4,%5,%6,%7},{%8,%9},{%0,%1,%2,%3};\n"
                    : "+f"(acc[2 * nb + 1][0]), "+f"(acc[2 * nb + 1][1]),
                      "+f"(acc[2 * nb + 1][2]), "+f"(acc[2 * nb + 1][3])
                    : "r"(a0), "r"(a1), "r"(a2), "r"(a3), "r"(bq2), "r"(bq3));
            }
        }
    }

    // stage cp tile bf16 [128][A_LD] into (own-warp rows of) A region,
    // and accumulate partial exp sums via shuffles.
    float* wred = (float*)(sm + GE_RED);
    {
        int c0 = wid * 16 + (lane >> 2);
#pragma unroll
        for (int t = 0; t < 8; t++) {
            int w = t * 8 + (lane & 3) * 2;
            *(__nv_bfloat162*)(sm + GE_A + c0 * 144 + w * 2) =
                __floats2bfloat162_rn(acc[t][0], acc[t][1]);
            *(__nv_bfloat162*)(sm + GE_A + (c0 + 8) * 144 + w * 2) =
                __floats2bfloat162_rn(acc[t][2], acc[t][3]);
            float sA = __expf(acc[t][0]) + __expf(acc[t][2]);
            float sB = __expf(acc[t][1]) + __expf(acc[t][3]);
            sA += __shfl_xor_sync(0xffffffffu, sA, 4);
            sB += __shfl_xor_sync(0xffffffffu, sB, 4);
            sA += __shfl_xor_sync(0xffffffffu, sA, 8);
            sB += __shfl_xor_sync(0xffffffffu, sB, 8);
            sA += __shfl_xor_sync(0xffffffffu, sA, 16);
            sB += __shfl_xor_sync(0xffffffffu, sB, 16);
            if (lane < 4) {
                wred[wid * 64 + t * 8 + (lane & 3) * 2]     = sA;
                wred[wid * 64 + t * 8 + (lane & 3) * 2 + 1] = sB;
            }
        }
    }
    __syncthreads();

    // coalesced cp write: each c-row = 128B contiguous (8 uint4)
    {
        int cbase = cT * 128;
        for (int i = tid; i < 1024; i += 256) {
            int c = i >> 3, q = i & 7;
            uint4 v = *(const uint4*)(sm + GE_A + c * 144 + q * 16);
            *((uint4*)(g_cp + ((size_t)(b * 512 + cbase + c) * 64 + h) * 64) + q) = v;
        }
    }
    if (tid < 64) {
        float s = wred[tid];
#pragma unroll
        for (int k = 1; k < 8; k++) s += wred[k * 64 + tid];
        g_psum[(((size_t)cT * 16 + b) * 64 + h) * 64 + tid] = s;
    }
}

// ---------------------------------------------------------------------------
// K3b: stencil conv3d (packed f32x2 FMA) + softmax-normalize + residual.
// Block = (16-c, 8-h) tile, 256 thr, 2c x 2h x 8w per thread, 3 CTAs/SM.
// ---------------------------------------------------------------------------
#define CV_XT_F   (18 * 10 * 64)            // tile floats
#define CV_BYTES  (CV_XT_F * 4 + 256)       // + packed weights

__global__ void __launch_bounds__(256, 3) k_conv(
    const float* __restrict__ x, const float* __restrict__ w3d,
    float* __restrict__ out) {
    extern __shared__ float xt[];            // [18 c][10 h][64 w]
    float* w3p = xt + CV_XT_F;               // 27 packed (k,k) pairs
    int h0 = blockIdx.x * 8;
    int c0 = blockIdx.y * 16;
    int b  = blockIdx.z;
    int tid = threadIdx.x;

    if (tid < 27) {
        float k = w3d[tid];
        w3p[2 * tid] = k; w3p[2 * tid + 1] = k;
    }

    // load halo tile (18c x 10h x 64w) via cp.async with zero-fill
    {
        unsigned dstb = s2u(xt);
        const float4* x4 = (const float4*)x;
        for (int i = tid; i < 2880; i += 256) {
            int w4 = i & 15, rest = i >> 4;
            int hi = rest % 10, ci = rest / 10;
            int cg = c0 - 1 + ci, hg = h0 - 1 + hi;
            bool ok = ((unsigned)cg < 512u) && ((unsigned)hg < 64u);
            const float4* src = ok ? (x4 + (((size_t)(b * 512 + cg) * 64 + hg) * 16 + w4)) : x4;
            int sz = ok ? 16 : 0;
            asm volatile("cp.async.cg.shared.global [%0], [%1], 16, %2;\n"
                         :: "r"(dstb + (unsigned)i * 16), "l"((const void*)src), "r"(sz));
        }
        asm volatile("cp.async.commit_group;\n" ::);
        asm volatile("cp.async.wait_group 0;\n" ::);
    }
    __syncthreads();

    int wg = tid & 7, hq = (tid >> 3) & 3, cq = tid >> 5;  // 2h, 2c per thread
    ull r[2][2][4];
#pragma unroll
    for (int i = 0; i < 2; i++)
#pragma unroll
        for (int j = 0; j < 2; j++)
#pragma unroll
            for (int p = 0; p < 4; p++) r[i][j][p] = 0ull;

#pragma unroll
    for (int ci = 0; ci < 4; ci++) {
#pragma unroll
        for (int hi = 0; hi < 4; hi++) {
            const float* row = xt + ((cq * 2 + ci) * 10 + (hq * 2 + hi)) * 64 + wg * 8;
            float4 m0 = *(const float4*)row;
            float4 m1 = *(const float4*)(row + 4);
            float left  = (wg == 0) ? 0.f : row[-1];
            float right = (wg == 7) ? 0.f : row[8];
            ull E0, E1, E2, E3, E4, O0, O1, O2, O3;
            PK2(E0, left, m0.x);  PK2(E1, m0.y, m0.z);
            PK2(E2, m0.w, m1.x);  PK2(E3, m1.y, m1.z);
            PK2(E4, m1.w, right);
            PK2(O0, m0.x, m0.y);  PK2(O1, m0.z, m0.w);
            PK2(O2, m1.x, m1.y);  PK2(O3, m1.z, m1.w);
#pragma unroll
            for (int dc = 0; dc < 3; dc++) {
                int cc = ci - dc;
                if (cc < 0 || cc > 1) continue;
#pragma unroll
                for (int dh = 0; dh < 3; dh++) {
                    int hh = hi - dh;
                    if (hh < 0 || hh > 1) continue;
                    int t = (dc * 3 + dh) * 3;
                    ull k0 = *(const ull*)(w3p + 2 * t);
                    ull k1 = *(const ull*)(w3p + 2 * t + 2);
                    ull k2 = *(const ull*)(w3p + 2 * t + 4);
                    FMA2(r[cc][hh][0], k0, E0); FMA2(r[cc][hh][0], k1, O0); FMA2(r[cc][hh][0], k2, E1);
                    FMA2(r[cc][hh][1], k0, E1); FMA2(r[cc][hh][1], k1, O1); FMA2(r[cc][hh][1], k2, E2);
                    FMA2(r[cc][hh][2], k0, E2); FMA2(r[cc][hh][2], k1, O2); FMA2(r[cc][hh][2], k2, E3);
                    FMA2(r[cc][hh][3], k0, E3); FMA2(r[cc][hh][3], k1, O3); FMA2(r[cc][hh][3], k2, E4);
                }
            }
        }
    }

    // epilogue: per hh compute inv, then o = res * exp(cp)*inv + x
#pragma unroll
    for (int hh = 0; hh < 2; hh++) {
        int h = h0 + hq * 2 + hh;
        float inv[8];
        {
            float4 s0 = make_float4(0.f, 0.f, 0.f, 0.f), s1 = s0;
#pragma unroll
            for (int ct = 0; ct < 4; ct++) {
                const float4* pp = (const float4*)(g_psum +
                    (((size_t)ct * 16 + b) * 64 + h) * 64 + wg * 8);
                float4 p0 = pp[0], p1 = pp[1];
                s0.x += p0.x; s0.y += p0.y; s0.z += p0.z; s0.w += p0.w;
                s1.x += p1.x; s1.y += p1.y; s1.z += p1.z; s1.w += p1.w;
            }
            inv[0] = 1.f / s0.x; inv[1] = 1.f / s0.y; inv[2] = 1.f / s0.z; inv[3] = 1.f / s0.w;
            inv[4] = 1.f / s1.x; inv[5] = 1.f / s1.y; inv[6] = 1.f / s1.z; inv[7] = 1.f / s1.w;
        }
#pragma unroll
        for (int cc = 0; cc < 2; cc++) {
            int c = c0 + cq * 2 + cc;
            const float* ctr = xt + ((cq * 2 + cc + 1) * 10 + (hq * 2 + hh + 1)) * 64 + wg * 8;
            float4 xi0 = *(const float4*)ctr;
            float4 xi1 = *(const float4*)(ctr + 4);
            uint4 cv = *(const uint4*)(g_cp + ((size_t)(b * 512 + c) * 64 + h) * 64 + wg * 8);
            const __nv_bfloat162* cpp = (const __nv_bfloat162*)&cv;
            float xin[8] = {xi0.x, xi0.y, xi0.z, xi0.w, xi1.x, xi1.y, xi1.z, xi1.w};
            float o[8];
#pragma unroll
            for (int p = 0; p < 4; p++) {
                float lo, hi;
                UPK2(lo, hi, r[cc][hh][p]);
                float2 cf = __bfloat1622float2(cpp[p]);
                o[2 * p]     = lo * (__expf(cf.x) * inv[2 * p])     + xin[2 * p];
                o[2 * p + 1] = hi * (__expf(cf.y) * inv[2 * p + 1]) + xin[2 * p + 1];
            }
            float* op = out + (((size_t)(b * 512 + c) * 64 + h) * 64 + wg * 8);
            *(float4*)(op)     = make_float4(o[0], o[1], o[2], o[3]);
            *(float4*)(op + 4) = make_float4(o[4], o[5], o[6], o[7]);
        }
    }
}

// ---------------------------------------------------------------------------
extern "C" void kernel_launch(void* const* d_in, const int* in_sizes, int n_in,
                              void* d_out, int out_size) {
    const float* x   = (const float*)d_in[0];
    const float* w_c = (const float*)d_in[1];
    const float* a_c = (const float*)d_in[2];
    const float* w_w = (const float*)d_in[3];
    const float* a_w = (const float*)d_in[4];
    const float* w_h = (const float*)d_in[5];
    const float* a_h = (const float*)d_in[6];
    const float* w3d = (const float*)d_in[7];
    float* out = (float*)d_out;

    cudaFuncSetAttribute(k_gemmE, cudaFuncAttributeMaxDynamicSharedMemorySize, GE_BYTES);
    cudaFuncSetAttribute(k_conv, cudaFuncAttributeMaxDynamicSharedMemorySize, CV_BYTES);

    k_reduce<<<Bn * Cn, 256>>>(x);
    k_branches<<<Bn, 256>>>(w_c, a_c, w_w, a_w, w_h, a_h);
    dim3 gridG(4, Hn, Bn);
    k_gemmE<<<gridG, 256, GE_BYTES>>>(0);
    dim3 gridC(8, 32, Bn);
    k_conv<<<gridC, 256, CV_BYTES>>>(x, w3d, out);
}

// round 8
// speedup vs baseline: 1.0607x; 1.0288x over previous
#include <cuda_runtime.h>
#include <cuda_bf16.h>
#include <cstdint>

#define Bn 16
#define Cn 512
#define Hn 64
#define Wn 64
#define Rn 64
#define A_LD 72   // padded bf16 row stride (144B = 9x16B, ldmatrix-friendly)

typedef unsigned long long ull;

// Scratch (device globals; no allocation allowed)
__device__ float g_sumC[Bn*Cn];
__device__ float g_partW[Bn*Cn*Wn];
__device__ float g_partH[Bn*Cn*Hn];
__device__ __align__(16) __nv_bfloat16 g_cAb[Bn*Cn*A_LD];  // A[b][c][r] bf16
__device__ float g_wout[Bn*Rn*Wn];  // [b][r][w]
__device__ float g_hout[Bn*Rn*Hn];  // [b][r][h]
__device__ __align__(16) __nv_bfloat16 g_cp[(size_t)Bn*Cn*Hn*Wn];  // logits bf16
__device__ float g_psum[4*Bn*Hn*Wn];  // partial exp-sums [cT][b][h][w]

__device__ __forceinline__ unsigned s2u(const void* p) {
    return (unsigned)__cvta_generic_to_shared(p);
}

// tied-operand f32x2 FMA: no extra MOVs
#define FMA2(d, a, bb) asm("fma.rn.f32x2 %0, %1, %2, %0;" : "+l"(d) : "l"(a), "l"(bb))
#define PK2(d, lo, hi) asm("mov.b64 %0, {%1, %2};" : "=l"(d) : "f"(lo), "f"(hi))
#define UPK2(lo, hi, v) asm("mov.b64 {%0, %1}, %2;" : "=f"(lo), "=f"(hi) : "l"(v))

// ---------------------------------------------------------------------------
// K1: per-(b,c) plane reductions
// ---------------------------------------------------------------------------
__global__ __launch_bounds__(256) void k_reduce(const float* __restrict__ x) {
    int plane = blockIdx.x;
    const float4* x4 = (const float4*)(x + (size_t)plane * 4096);
    int tid = threadIdx.x;

    __shared__ float4 s4[256];
    __shared__ float  sh[256][4];

    float4 wacc = make_float4(0.f, 0.f, 0.f, 0.f);
    float hacc[4];
#pragma unroll
    for (int k = 0; k < 4; k++) {
        float4 f = x4[tid + 256 * k];
        wacc.x += f.x; wacc.y += f.y; wacc.z += f.z; wacc.w += f.w;
        hacc[k] = f.x + f.y + f.z + f.w;
    }
    s4[tid] = wacc;
    sh[tid][0] = hacc[0]; sh[tid][1] = hacc[1];
    sh[tid][2] = hacc[2]; sh[tid][3] = hacc[3];
    __syncthreads();

    if (tid < 16) {
        float4 t = s4[tid];
#pragma unroll
        for (int j = 1; j < 16; j++) {
            float4 u = s4[tid + 16 * j];
            t.x += u.x; t.y += u.y; t.z += u.z; t.w += u.w;
        }
        ((float4*)g_partW)[plane * 16 + tid] = t;
        s4[tid] = t;
    }
    if (tid >= 64 && tid < 128) {
        int h = tid - 64;
        int base = (h & 15) * 16;
        int k = h >> 4;
        float s = 0.f;
#pragma unroll
        for (int j = 0; j < 16; j++) s += sh[base + j][k];
        g_partH[plane * 64 + h] = s;
    }
    __syncthreads();
    if (tid == 0) {
        float tot = 0.f;
#pragma unroll
        for (int j = 0; j < 16; j++) {
            float4 u = s4[j];
            tot += u.x + u.y + u.z + u.w;
        }
        g_sumC[plane] = tot;
    }
}

// ---------------------------------------------------------------------------
// K2: finish gap means, 3-tap convs + PReLU
// ---------------------------------------------------------------------------
__global__ __launch_bounds__(256) void k_branches(
    const float* __restrict__ w_c, const float* __restrict__ a_c,
    const float* __restrict__ w_w, const float* __restrict__ a_w,
    const float* __restrict__ w_h, const float* __restrict__ a_h) {
    int b = blockIdx.x, tid = threadIdx.x;
    __shared__ float gc[Cn + 2];
    __shared__ float gw[Wn + 2];
    __shared__ float gh[Hn + 2];
    __shared__ float red[4][64];

    for (int i = tid; i < Cn; i += 256)
        gc[i + 1] = g_sumC[b * Cn + i] * (1.f / 4096.f);
    if (tid == 0) {
        gc[0] = 0.f; gc[Cn + 1] = 0.f;
        gw[0] = 0.f; gw[Wn + 1] = 0.f;
        gh[0] = 0.f; gh[Hn + 1] = 0.f;
    }
    {
        int q = tid >> 6, w = tid & 63;
        float s = 0.f;
        const float* p = g_partW + ((size_t)(b * Cn + q * 128)) * 64 + w;
#pragma unroll 4
        for (int c = 0; c < 128; c++) s += p[c * 64];
        red[q][w] = s;
    }
    __syncthreads();
    if (tid < 64)
        gw[tid + 1] = (red[0][tid] + red[1][tid] + red[2][tid] + red[3][tid]) * (1.f / 32768.f);
    __syncthreads();
    {
        int q = tid >> 6, hh = tid & 63;
        float s = 0.f;
        const float* p = g_partH + ((size_t)(b * Cn + q * 128)) * 64 + hh;
#pragma unroll 4
        for (int c = 0; c < 128; c++) s += p[c * 64];
        red[q][hh] = s;
    }
    __syncthreads();
    if (tid < 64)
        gh[tid + 1] = (red[0][tid] + red[1][tid] + red[2][tid] + red[3][tid]) * (1.f / 32768.f);
    __syncthreads();

    float acv = a_c[0], awv = a_w[0], ahv = a_h[0];
    for (int i = tid; i < Rn * Cn; i += 256) {
        int r = i >> 9, c = i & 511;
        float v = w_c[r * 3] * gc[c] + w_c[r * 3 + 1] * gc[c + 1] + w_c[r * 3 + 2] * gc[c + 2];
        v = (v >= 0.f) ? v : acv * v;
        g_cAb[((size_t)(b * Cn + c)) * A_LD + r] = __float2bfloat16(v);
    }
    for (int i = tid; i < Rn * Wn; i += 256) {
        int r = i >> 6, w = i & 63;
        float v = w_w[r * 3] * gw[w] + w_w[r * 3 + 1] * gw[w + 1] + w_w[r * 3 + 2] * gw[w + 2];
        g_wout[b * Rn * Wn + i] = (v >= 0.f) ? v : awv * v;
        float v2 = w_h[r * 3] * gh[w] + w_h[r * 3 + 1] * gh[w + 1] + w_h[r * 3 + 2] * gh[w + 2];
        g_hout[b * Rn * Hn + i] = (v2 >= 0.f) ? v2 : ahv * v2;
    }
}

// ---------------------------------------------------------------------------
// K3a v2: block = (cT 128-c, 8-h group, b). A staged once, A-fragments
// hoisted to registers, per-h: S build -> MMA -> cp store -> exp psum.
// ---------------------------------------------------------------------------
#define GE_A    0                 // bf16 [128][A_LD] = 18432
#define GE_S    18432             // bf16 [64][A_LD]  = 9216
#define GE_WO   27648             // f32 [64][64]     = 16384
#define GE_HO   44032             // f32 [64][8]      = 2048
#define GE_RED  46080             // f32 [8][64]      = 2048
#define GE_BYTES 48128

__global__ void __launch_bounds__(256) k_gemmE(int dummy) {
    extern __shared__ char sm[];
    int cT = blockIdx.x, h0 = blockIdx.y * 8, b = blockIdx.z;
    int tid = threadIdx.x;
    int lane = tid & 31, wid = tid >> 5;

    // one-time staging: A tile, wo (f32), ho (f32, 8 h values per r)
    {
        const uint4* src = (const uint4*)(g_cAb + ((size_t)b * 512 + cT * 128) * A_LD);
        uint4* dst = (uint4*)(sm + GE_A);
        for (int i = tid; i < 1152; i += 256) dst[i] = src[i];
        const float4* wsrc = (const float4*)(g_wout + (size_t)b * 4096);
        float4* wdst = (float4*)(sm + GE_WO);
        for (int i = tid; i < 1024; i += 256) wdst[i] = wsrc[i];
        float* ho = (float*)(sm + GE_HO);
        const float* hsrc = g_hout + (size_t)b * 4096 + h0;
#pragma unroll
        for (int k = 0; k < 2; k++) {
            int j = tid * 2 + k;           // j = r*8 + hh
            ho[j] = hsrc[(j >> 3) * 64 + (j & 7)];
        }
    }
    __syncthreads();

    // hoist A fragments (constant across the h loop)
    unsigned afr[4][4];
    {
        unsigned aBase = s2u(sm + GE_A);
        int cb = wid * 16;
        int aRow = lane & 15;
        unsigned aColOff = (unsigned)(lane >> 4) * 16u;
#pragma unroll
        for (int ks = 0; ks < 4; ks++) {
            unsigned ad = aBase + (unsigned)((cb + aRow) * A_LD + ks * 16) * 2u + aColOff;
            asm volatile("ldmatrix.sync.aligned.m8n8.x4.shared.b16 {%0,%1,%2,%3}, [%4];\n"
                         : "=r"(afr[ks][0]), "=r"(afr[ks][1]),
                           "=r"(afr[ks][2]), "=r"(afr[ks][3])
                         : "r"(ad));
        }
    }

    __nv_bfloat16* S = (__nv_bfloat16*)(sm + GE_S);
    const float* wo_s = (const float*)(sm + GE_WO);
    const float* ho_s = (const float*)(sm + GE_HO);
    float* wred = (float*)(sm + GE_RED);
    unsigned sBase = s2u(sm + GE_S);
    int bRowOff = (lane & 7) + ((lane & 8) ? 8 : 0);
    int bColOff = (lane & 16) ? 8 : 0;

    for (int hj = 0; hj < 8; hj++) {
        int h = h0 + hj;
        // build S[r][w] = ho[r][h] * wo[r][w]
        for (int i = tid; i < 4096; i += 256) {
            int r = i >> 6, w = i & 63;
            S[r * A_LD + w] = __float2bfloat16(ho_s[r * 8 + hj] * wo_s[i]);
        }
        __syncthreads();

        float acc[8][4];
#pragma unroll
        for (int t = 0; t < 8; t++)
#pragma unroll
            for (int q = 0; q < 4; q++) acc[t][q] = 0.f;

#pragma unroll
        for (int ks = 0; ks < 4; ks++) {
            int k0 = ks * 16;
#pragma unroll
            for (int nb = 0; nb < 4; nb++) {
                unsigned bd = sBase + (unsigned)((k0 + bRowOff) * A_LD + nb * 16 + bColOff) * 2u;
                unsigned bq0, bq1, bq2, bq3;
                asm volatile("ldmatrix.sync.aligned.m8n8.x4.trans.shared.b16 {%0,%1,%2,%3}, [%4];\n"
                             : "=r"(bq0), "=r"(bq1), "=r"(bq2), "=r"(bq3) : "r"(bd));
                asm volatile(
                    "mma.sync.aligned.m16n8k16.row.col.f32.bf16.bf16.f32 "
                    "{%0,%1,%2,%3},{%4,%5,%6,%7},{%8,%9},{%0,%1,%2,%3};\n"
                    : "+f"(acc[2 * nb][0]), "+f"(acc[2 * nb][1]),
                      "+f"(acc[2 * nb][2]), "+f"(acc[2 * nb][3])
                    : "r"(afr[ks][0]), "r"(afr[ks][1]), "r"(afr[ks][2]), "r"(afr[ks][3]),
                      "r"(bq0), "r"(bq1));
                asm volatile(
                    "mma.sync.aligned.m16n8k16.row.col.f32.bf16.bf16.f32 "
                    "{%0,%1,%2,%3},{%4,%5,%6,%7},{%8,%9},{%0,%1,%2,%3};\n"
                    : "+f"(acc[2 * nb + 1][0]), "+f"(acc[2 * nb + 1][1]),
                      "+f"(acc[2 * nb + 1][2]), "+f"(acc[2 * nb + 1][3])
                    : "r"(afr[ks][0]), "r"(afr[ks][1]), "r"(afr[ks][2]), "r"(afr[ks][3]),
                      "r"(bq2), "r"(bq3));
            }
        }

        // cp store (4-lane groups write 16B contiguous) + exp partial sums
        {
            int c_lo = cT * 128 + wid * 16 + (lane >> 2);
#pragma unroll
            for (int t = 0; t < 8; t++) {
                int w = t * 8 + (lane & 3) * 2;
                *(__nv_bfloat162*)(g_cp + ((size_t)(b * 512 + c_lo) * 64 + h) * 64 + w) =
                    __floats2bfloat162_rn(acc[t][0], acc[t][1]);
                *(__nv_bfloat162*)(g_cp + ((size_t)(b * 512 + c_lo + 8) * 64 + h) * 64 + w) =
                    __floats2bfloat162_rn(acc[t][2], acc[t][3]);
                float sA = __expf(acc[t][0]) + __expf(acc[t][2]);
                float sB = __expf(acc[t][1]) + __expf(acc[t][3]);
                sA += __shfl_xor_sync(0xffffffffu, sA, 4);
                sB += __shfl_xor_sync(0xffffffffu, sB, 4);
                sA += __shfl_xor_sync(0xffffffffu, sA, 8);
                sB += __shfl_xor_sync(0xffffffffu, sB, 8);
                sA += __shfl_xor_sync(0xffffffffu, sA, 16);
                sB += __shfl_xor_sync(0xffffffffu, sB, 16);
                if (lane < 4) {
                    wred[wid * 64 + w]     = sA;
                    wred[wid * 64 + w + 1] = sB;
                }
            }
        }
        __syncthreads();
        if (tid < 64) {
            float s = wred[tid];
#pragma unroll
            for (int k = 1; k < 8; k++) s += wred[k * 64 + tid];
            g_psum[(((size_t)cT * 16 + b) * 64 + h) * 64 + tid] = s;
        }
        __syncthreads();
    }
}

// ---------------------------------------------------------------------------
// K3b: stencil conv3d (packed f32x2 FMA, tied operands) + normalize + resid.
// ---------------------------------------------------------------------------
#define CV_XT_F   (18 * 10 * 64)            // tile floats
#define CV_BYTES  (CV_XT_F * 4 + 256)       // + packed weights

__global__ void __launch_bounds__(256, 3) k_conv(
    const float* __restrict__ x, const float* __restrict__ w3d,
    float* __restrict__ out) {
    extern __shared__ float xt[];            // [18 c][10 h][64 w]
    float* w3p = xt + CV_XT_F;               // 27 packed (k,k) pairs
    int h0 = blockIdx.x * 8;
    int c0 = blockIdx.y * 16;
    int b  = blockIdx.z;
    int tid = threadIdx.x;

    if (tid < 27) {
        float k = w3d[tid];
        w3p[2 * tid] = k; w3p[2 * tid + 1] = k;
    }

    // load halo tile (18c x 10h x 64w) via cp.async with zero-fill
    {
        unsigned dstb = s2u(xt);
        const float4* x4 = (const float4*)x;
        for (int i = tid; i < 2880; i += 256) {
            int w4 = i & 15, rest = i >> 4;
            int hi = rest % 10, ci = rest / 10;
            int cg = c0 - 1 + ci, hg = h0 - 1 + hi;
            bool ok = ((unsigned)cg < 512u) && ((unsigned)hg < 64u);
            const float4* src = ok ? (x4 + (((size_t)(b * 512 + cg) * 64 + hg) * 16 + w4)) : x4;
            int sz = ok ? 16 : 0;
            asm volatile("cp.async.cg.shared.global [%0], [%1], 16, %2;\n"
                         :: "r"(dstb + (unsigned)i * 16), "l"((const void*)src), "r"(sz));
        }
        asm volatile("cp.async.commit_group;\n" ::);
        asm volatile("cp.async.wait_group 0;\n" ::);
    }
    __syncthreads();

    int wg = tid & 7, hq = (tid >> 3) & 3, cq = tid >> 5;  // 2h, 2c per thread
    ull r[2][2][4];
#pragma unroll
    for (int i = 0; i < 2; i++)
#pragma unroll
        for (int j = 0; j < 2; j++)
#pragma unroll
            for (int p = 0; p < 4; p++) r[i][j][p] = 0ull;

#pragma unroll
    for (int ci = 0; ci < 4; ci++) {
#pragma unroll
        for (int hi = 0; hi < 4; hi++) {
            const float* row = xt + ((cq * 2 + ci) * 10 + (hq * 2 + hi)) * 64 + wg * 8;
            float4 m0 = *(const float4*)row;
            float4 m1 = *(const float4*)(row + 4);
            float left  = (wg == 0) ? 0.f : row[-1];
            float right = (wg == 7) ? 0.f : row[8];
            ull E0, E1, E2, E3, E4, O0, O1, O2, O3;
            PK2(E0, left, m0.x);  PK2(E1, m0.y, m0.z);
            PK2(E2, m0.w, m1.x);  PK2(E3, m1.y, m1.z);
            PK2(E4, m1.w, right);
            PK2(O0, m0.x, m0.y);  PK2(O1, m0.z, m0.w);
            PK2(O2, m1.x, m1.y);  PK2(O3, m1.z, m1.w);
#pragma unroll
            for (int dc = 0; dc < 3; dc++) {
                int cc = ci - dc;
                if (cc < 0 || cc > 1) continue;
#pragma unroll
                for (int dh = 0; dh < 3; dh++) {
                    int hh = hi - dh;
                    if (hh < 0 || hh > 1) continue;
                    int t = (dc * 3 + dh) * 3;
                    ull k0 = *(const ull*)(w3p + 2 * t);
                    ull k1 = *(const ull*)(w3p + 2 * t + 2);
                    ull k2 = *(const ull*)(w3p + 2 * t + 4);
                    FMA2(r[cc][hh][0], k0, E0); FMA2(r[cc][hh][0], k1, O0); FMA2(r[cc][hh][0], k2, E1);
                    FMA2(r[cc][hh][1], k0, E1); FMA2(r[cc][hh][1], k1, O1); FMA2(r[cc][hh][1], k2, E2);
                    FMA2(r[cc][hh][2], k0, E2); FMA2(r[cc][hh][2], k1, O2); FMA2(r[cc][hh][2], k2, E3);
                    FMA2(r[cc][hh][3], k0, E3); FMA2(r[cc][hh][3], k1, O3); FMA2(r[cc][hh][3], k2, E4);
                }
            }
        }
    }

    // epilogue: per hh compute inv, then o = res * exp(cp)*inv + x
#pragma unroll
    for (int hh = 0; hh < 2; hh++) {
        int h = h0 + hq * 2 + hh;
        float inv[8];
        {
            float4 s0 = make_float4(0.f, 0.f, 0.f, 0.f), s1 = s0;
#pragma unroll
            for (int ct = 0; ct < 4; ct++) {
                const float4* pp = (const float4*)(g_psum +
                    (((size_t)ct * 16 + b) * 64 + h) * 64 + wg * 8);
                float4 p0 = pp[0], p1 = pp[1];
                s0.x += p0.x; s0.y += p0.y; s0.z += p0.z; s0.w += p0.w;
                s1.x += p1.x; s1.y += p1.y; s1.z += p1.z; s1.w += p1.w;
            }
            inv[0] = 1.f / s0.x; inv[1] = 1.f / s0.y; inv[2] = 1.f / s0.z; inv[3] = 1.f / s0.w;
            inv[4] = 1.f / s1.x; inv[5] = 1.f / s1.y; inv[6] = 1.f / s1.z; inv[7] = 1.f / s1.w;
        }
#pragma unroll
        for (int cc = 0; cc < 2; cc++) {
            int c = c0 + cq * 2 + cc;
            const float* ctr = xt + ((cq * 2 + cc + 1) * 10 + (hq * 2 + hh + 1)) * 64 + wg * 8;
            float4 xi0 = *(const float4*)ctr;
            float4 xi1 = *(const float4*)(ctr + 4);
            uint4 cv = *(const uint4*)(g_cp + ((size_t)(b * 512 + c) * 64 + h) * 64 + wg * 8);
            const __nv_bfloat162* cpp = (const __nv_bfloat162*)&cv;
            float xin[8] = {xi0.x, xi0.y, xi0.z, xi0.w, xi1.x, xi1.y, xi1.z, xi1.w};
            float o[8];
#pragma unroll
            for (int p = 0; p < 4; p++) {
                float lo, hi;
                UPK2(lo, hi, r[cc][hh][p]);
                float2 cf = __bfloat1622float2(cpp[p]);
                o[2 * p]     = lo * (__expf(cf.x) * inv[2 * p])     + xin[2 * p];
                o[2 * p + 1] = hi * (__expf(cf.y) * inv[2 * p + 1]) + xin[2 * p + 1];
            }
            float* op = out + (((size_t)(b * 512 + c) * 64 + h) * 64 + wg * 8);
            *(float4*)(op)     = make_float4(o[0], o[1], o[2], o[3]);
            *(float4*)(op + 4) = make_float4(o[4], o[5], o[6], o[7]);
        }
    }
}

// ---------------------------------------------------------------------------
extern "C" void kernel_launch(void* const* d_in, const int* in_sizes, int n_in,
                              void* d_out, int out_size) {
    const float* x   = (const float*)d_in[0];
    const float* w_c = (const float*)d_in[1];
    const float* a_c = (const float*)d_in[2];
    const float* w_w = (const float*)d_in[3];
    const float* a_w = (const float*)d_in[4];
    const float* w_h = (const float*)d_in[5];
    const float* a_h = (const float*)d_in[6];
    const float* w3d = (const float*)d_in[7];
    float* out = (float*)d_out;

    cudaFuncSetAttribute(k_gemmE, cudaFuncAttributeMaxDynamicSharedMemorySize, GE_BYTES);
    cudaFuncSetAttribute(k_conv, cudaFuncAttributeMaxDynamicSharedMemorySize, CV_BYTES);

    k_reduce<<<Bn * Cn, 256>>>(x);
    k_branches<<<Bn, 256>>>(w_c, a_c, w_w, a_w, w_h, a_h);
    dim3 gridG(4, 8, Bn);
    k_gemmE<<<gridG, 256, GE_BYTES>>>(0);
    dim3 gridC(8, 32, Bn);
    k_conv<<<gridC, 256, CV_BYTES>>>(x, w3d, out);
}

// round 9
// speedup vs baseline: 1.1608x; 1.0944x over previous
#include <cuda_runtime.h>
#include <cuda_bf16.h>
#include <cstdint>

#define Bn 16
#define Cn 512
#define Hn 64
#define Wn 64
#define Rn 64
#define A_LD 72    // bf16 row stride for A (144B)
#define GB_LD 264  // bf16 row stride for B tile (528B = 33x16B, conflict-free)

typedef unsigned long long ull;

// Scratch (device globals; no allocation allowed)
__device__ float g_sumC[Bn*Cn];
__device__ float g_partW[Bn*Cn*Wn];
__device__ float g_partH[Bn*Cn*Hn];
__device__ float g_gap2[2*Bn*32*64];   // [sel][b][32 c-part][w]
__device__ __align__(16) __nv_bfloat16 g_cAb[Bn*Cn*A_LD];  // A[b][c][r] bf16
__device__ float g_wout[Bn*Rn*Wn];  // [b][r][w]
__device__ float g_hout[Bn*Rn*Hn];  // [b][r][h]
__device__ __align__(16) __nv_bfloat16 g_cp[(size_t)Bn*Cn*Hn*Wn];  // logits bf16
__device__ float g_psum[4*Bn*Hn*Wn];  // partial exp-sums [cT][b][h][w]

__device__ __forceinline__ unsigned s2u(const void* p) {
    return (unsigned)__cvta_generic_to_shared(p);
}

#define FMA2(d, a, bb) asm("fma.rn.f32x2 %0, %1, %2, %0;" : "+l"(d) : "l"(a), "l"(bb))
#define PK2(d, lo, hi) asm("mov.b64 %0, {%1, %2};" : "=l"(d) : "f"(lo), "f"(hi))
#define UPK2(lo, hi, v) asm("mov.b64 {%0, %1}, %2;" : "=f"(lo), "=f"(hi) : "l"(v))

// ---------------------------------------------------------------------------
// K1: per-(b,c) plane reductions
// ---------------------------------------------------------------------------
__global__ __launch_bounds__(256) void k_reduce(const float* __restrict__ x) {
    int plane = blockIdx.x;
    const float4* x4 = (const float4*)(x + (size_t)plane * 4096);
    int tid = threadIdx.x;

    __shared__ float4 s4[256];
    __shared__ float  sh[256][4];

    float4 wacc = make_float4(0.f, 0.f, 0.f, 0.f);
    float hacc[4];
#pragma unroll
    for (int k = 0; k < 4; k++) {
        float4 f = x4[tid + 256 * k];
        wacc.x += f.x; wacc.y += f.y; wacc.z += f.z; wacc.w += f.w;
        hacc[k] = f.x + f.y + f.z + f.w;
    }
    s4[tid] = wacc;
    sh[tid][0] = hacc[0]; sh[tid][1] = hacc[1];
    sh[tid][2] = hacc[2]; sh[tid][3] = hacc[3];
    __syncthreads();

    if (tid < 16) {
        float4 t = s4[tid];
#pragma unroll
        for (int j = 1; j < 16; j++) {
            float4 u = s4[tid + 16 * j];
            t.x += u.x; t.y += u.y; t.z += u.z; t.w += u.w;
        }
        ((float4*)g_partW)[plane * 16 + tid] = t;
        s4[tid] = t;
    }
    if (tid >= 64 && tid < 128) {
        int h = tid - 64;
        int base = (h & 15) * 16;
        int k = h >> 4;
        float s = 0.f;
#pragma unroll
        for (int j = 0; j < 16; j++) s += sh[base + j][k];
        g_partH[plane * 64 + h] = s;
    }
    __syncthreads();
    if (tid == 0) {
        float tot = 0.f;
#pragma unroll
        for (int j = 0; j < 16; j++) {
            float4 u = s4[j];
            tot += u.x + u.y + u.z + u.w;
        }
        g_sumC[plane] = tot;
    }
}

// ---------------------------------------------------------------------------
// K1b: parallel strided gap reductions (replaces slow part of k_branches)
// grid (16 b, 8 cq, 2 sel), 256 thr; each thread sums 16 c values.
// ---------------------------------------------------------------------------
__global__ __launch_bounds__(256) void k_gap(int dummy) {
    int b = blockIdx.x, cq = blockIdx.y, sel = blockIdx.z;
    int tid = threadIdx.x;
    int w = tid & 63, cs = tid >> 6;
    const float* src = sel ? g_partH : g_partW;
    const float* p = src + ((size_t)(b * 512 + cq * 64 + cs * 16)) * 64 + w;
    float s = 0.f;
#pragma unroll
    for (int k = 0; k < 16; k++) s += p[k * 64];
    g_gap2[((size_t)(sel * 16 + b) * 32 + cq * 4 + cs) * 64 + w] = s;
}

// ---------------------------------------------------------------------------
// K2: finish gap means, 3-tap convs + PReLU
// ---------------------------------------------------------------------------
__global__ __launch_bounds__(256) void k_branches(
    const float* __restrict__ w_c, const float* __restrict__ a_c,
    const float* __restrict__ w_w, const float* __restrict__ a_w,
    const float* __restrict__ w_h, const float* __restrict__ a_h) {
    int b = blockIdx.x, tid = threadIdx.x;
    __shared__ float gc[Cn + 2];
    __shared__ float gw[Wn + 2];
    __shared__ float gh[Hn + 2];
    __shared__ float red[4][64];

    for (int i = tid; i < Cn; i += 256)
        gc[i + 1] = g_sumC[b * Cn + i] * (1.f / 4096.f);
    if (tid == 0) {
        gc[0] = 0.f; gc[Cn + 1] = 0.f;
        gw[0] = 0.f; gw[Wn + 1] = 0.f;
        gh[0] = 0.f; gh[Hn + 1] = 0.f;
    }
    {
        int q = tid >> 6, w = tid & 63;
        const float* p = g_gap2 + ((size_t)(b) * 32 + q * 8) * 64 + w;
        float s = 0.f;
#pragma unroll
        for (int j = 0; j < 8; j++) s += p[j * 64];
        red[q][w] = s;
    }
    __syncthreads();
    if (tid < 64)
        gw[tid + 1] = (red[0][tid] + red[1][tid] + red[2][tid] + red[3][tid]) * (1.f / 32768.f);
    __syncthreads();
    {
        int q = tid >> 6, w = tid & 63;
        const float* p = g_gap2 + ((size_t)(16 + b) * 32 + q * 8) * 64 + w;
        float s = 0.f;
#pragma unroll
        for (int j = 0; j < 8; j++) s += p[j * 64];
        red[q][w] = s;
    }
    __syncthreads();
    if (tid < 64)
        gh[tid + 1] = (red[0][tid] + red[1][tid] + red[2][tid] + red[3][tid]) * (1.f / 32768.f);
    __syncthreads();

    float acv = a_c[0], awv = a_w[0], ahv = a_h[0];
    for (int i = tid; i < Rn * Cn; i += 256) {
        int r = i >> 9, c = i & 511;
        float v = w_c[r * 3] * gc[c] + w_c[r * 3 + 1] * gc[c + 1] + w_c[r * 3 + 2] * gc[c + 2];
        v = (v >= 0.f) ? v : acv * v;
        g_cAb[((size_t)(b * Cn + c)) * A_LD + r] = __float2bfloat16(v);
    }
    for (int i = tid; i < Rn * Wn; i += 256) {
        int r = i >> 6, w = i & 63;
        float v = w_w[r * 3] * gw[w] + w_w[r * 3 + 1] * gw[w + 1] + w_w[r * 3 + 2] * gw[w + 2];
        g_wout[b * Rn * Wn + i] = (v >= 0.f) ? v : awv * v;
        float v2 = w_h[r * 3] * gh[w] + w_h[r * 3 + 1] * gh[w + 1] + w_h[r * 3 + 2] * gh[w + 2];
        g_hout[b * Rn * Hn + i] = (v2 >= 0.f) ? v2 : ahv * v2;
    }
}

// ---------------------------------------------------------------------------
// K3a v3: block = (cT 128-c, 4-h group, b). B tile [64 r][4h*64w] bf16 built
// ONCE; h-loop is pure ldmatrix+MMA+store with no internal barriers.
// ---------------------------------------------------------------------------
#define GE_A    0        // bf16 [128][A_LD] = 18432
#define GE_B    18432    // bf16 [64][GB_LD] = 33792
#define GE_WO   52224    // f32 [64][64] = 16384 ; reused as wred [4][8][64]
#define GE_HO   68608    // f32 [64][4]  = 1024
#define GE_BYTES 69632

__global__ void __launch_bounds__(256) k_gemmE(int dummy) {
    extern __shared__ char sm[];
    int cT = blockIdx.x, h0 = blockIdx.y * 4, b = blockIdx.z;
    int tid = threadIdx.x;
    int lane = tid & 31, wid = tid >> 5;

    float* wo_s = (float*)(sm + GE_WO);
    float* ho_s = (float*)(sm + GE_HO);

    // stage A, wo, ho
    {
        const uint4* src = (const uint4*)(g_cAb + ((size_t)b * 512 + cT * 128) * A_LD);
        uint4* dst = (uint4*)(sm + GE_A);
        for (int i = tid; i < 1152; i += 256) dst[i] = src[i];
        const float4* wsrc = (const float4*)(g_wout + (size_t)b * 4096);
        float4* wdst = (float4*)wo_s;
        for (int i = tid; i < 1024; i += 256) wdst[i] = wsrc[i];
        int r = tid >> 2, hh = tid & 3;
        ho_s[tid] = g_hout[(size_t)b * 4096 + r * 64 + h0 + hh];
    }
    __syncthreads();

    // hoist A fragments
    unsigned afr[4][4];
    {
        unsigned aBase = s2u(sm + GE_A);
        int cb = wid * 16;
        int aRow = lane & 15;
        unsigned aColOff = (unsigned)(lane >> 4) * 16u;
#pragma unroll
        for (int ks = 0; ks < 4; ks++) {
            unsigned ad = aBase + (unsigned)((cb + aRow) * A_LD + ks * 16) * 2u + aColOff;
            asm volatile("ldmatrix.sync.aligned.m8n8.x4.shared.b16 {%0,%1,%2,%3}, [%4];\n"
                         : "=r"(afr[ks][0]), "=r"(afr[ks][1]),
                           "=r"(afr[ks][2]), "=r"(afr[ks][3])
                         : "r"(ad));
        }
    }

    // build B once: B[r][hj*64+w] = ho[r][hj] * wo[r][w]
    {
        __nv_bfloat16* B = (__nv_bfloat16*)(sm + GE_B);
        for (int i = tid; i < 8192; i += 256) {
            int r = i >> 7, col = (i & 127) * 2;
            int hj = col >> 6, w = col & 63;
            float hv = ho_s[r * 4 + hj];
            *(__nv_bfloat162*)(B + r * GB_LD + col) =
                __floats2bfloat162_rn(hv * wo_s[r * 64 + w], hv * wo_s[r * 64 + w + 1]);
        }
    }
    __syncthreads();

    float* wred = wo_s;  // reuse (wo dead after B build)
    unsigned sBase = s2u(sm + GE_B);
    int bRowOff = (lane & 7) + ((lane & 8) ? 8 : 0);
    int bColOff = (lane & 16) ? 8 : 0;

#pragma unroll
    for (int hj = 0; hj < 4; hj++) {
        int h = h0 + hj;
        float acc[8][4];
#pragma unroll
        for (int t = 0; t < 8; t++)
#pragma unroll
            for (int q = 0; q < 4; q++) acc[t][q] = 0.f;

#pragma unroll
        for (int ks = 0; ks < 4; ks++) {
            int k0 = ks * 16;
#pragma unroll
            for (int nb = 0; nb < 4; nb++) {
                unsigned bd = sBase +
                    (unsigned)((k0 + bRowOff) * GB_LD + hj * 64 + nb * 16 + bColOff) * 2u;
                unsigned bq0, bq1, bq2, bq3;
                asm volatile("ldmatrix.sync.aligned.m8n8.x4.trans.shared.b16 {%0,%1,%2,%3}, [%4];\n"
                             : "=r"(bq0), "=r"(bq1), "=r"(bq2), "=r"(bq3) : "r"(bd));
                asm volatile(
                    "mma.sync.aligned.m16n8k16.row.col.f32.bf16.bf16.f32 "
                    "{%0,%1,%2,%3},{%4,%5,%6,%7},{%8,%9},{%0,%1,%2,%3};\n"
                    : "+f"(acc[2 * nb][0]), "+f"(acc[2 * nb][1]),
                      "+f"(acc[2 * nb][2]), "+f"(acc[2 * nb][3])
                    : "r"(afr[ks][0]), "r"(afr[ks][1]), "r"(afr[ks][2]), "r"(afr[ks][3]),
                      "r"(bq0), "r"(bq1));
                asm volatile(
                    "mma.sync.aligned.m16n8k16.row.col.f32.bf16.bf16.f32 "
                    "{%0,%1,%2,%3},{%4,%5,%6,%7},{%8,%9},{%0,%1,%2,%3};\n"
                    : "+f"(acc[2 * nb + 1][0]), "+f"(acc[2 * nb + 1][1]),
                      "+f"(acc[2 * nb + 1][2]), "+f"(acc[2 * nb + 1][3])
                    : "r"(afr[ks][0]), "r"(afr[ks][1]), "r"(afr[ks][2]), "r"(afr[ks][3]),
                      "r"(bq2), "r"(bq3));
            }
        }

        // cp stores (quad writes 16B contiguous) + per-warp exp partials
        int c_lo = cT * 128 + wid * 16 + (lane >> 2);
#pragma unroll
        for (int t = 0; t < 8; t++) {
            int w = t * 8 + (lane & 3) * 2;
            *(__nv_bfloat162*)(g_cp + ((size_t)(b * 512 + c_lo) * 64 + h) * 64 + w) =
                __floats2bfloat162_rn(acc[t][0], acc[t][1]);
            *(__nv_bfloat162*)(g_cp + ((size_t)(b * 512 + c_lo + 8) * 64 + h) * 64 + w) =
                __floats2bfloat162_rn(acc[t][2], acc[t][3]);
            float sA = __expf(acc[t][0]) + __expf(acc[t][2]);
            float sB = __expf(acc[t][1]) + __expf(acc[t][3]);
            sA += __shfl_xor_sync(0xffffffffu, sA, 4);
            sB += __shfl_xor_sync(0xffffffffu, sB, 4);
            sA += __shfl_xor_sync(0xffffffffu, sA, 8);
            sB += __shfl_xor_sync(0xffffffffu, sB, 8);
            sA += __shfl_xor_sync(0xffffffffu, sA, 16);
            sB += __shfl_xor_sync(0xffffffffu, sB, 16);
            if (lane < 4) {
                wred[(hj * 8 + wid) * 64 + w]     = sA;
                wred[(hj * 8 + wid) * 64 + w + 1] = sB;
            }
        }
    }
    __syncthreads();

    // final psum reduce: 256 threads = 4 h x 64 w
    {
        int hj = tid >> 6, w = tid & 63;
        float s = 0.f;
#pragma unroll
        for (int k = 0; k < 8; k++) s += wred[(hj * 8 + k) * 64 + w];
        g_psum[(((size_t)cT * 16 + b) * 64 + h0 + hj) * 64 + w] = s;
    }
}

// ---------------------------------------------------------------------------
// K3b: stencil conv3d, R5 layout (8c x 8w per thread) + packed f32x2 FMA,
// weights hoisted per-dhi. 2048 blocks, 2 CTAs/SM.
// ---------------------------------------------------------------------------
#define CV_XT_F   (34 * 10 * 64)
#define CV_BYTES  (CV_XT_F * 4 + 256)

__global__ void __launch_bounds__(256, 2) k_conv(
    const float* __restrict__ x, const float* __restrict__ w3d,
    float* __restrict__ out) {
    extern __shared__ float xt[];   // [34 c][10 h][64 w]
    float* w3p = xt + CV_XT_F;      // 27 packed (k,k) pairs
    int h0 = blockIdx.x * 8;
    int c0 = blockIdx.y * 32;
    int b  = blockIdx.z;
    int tid = threadIdx.x;

    if (tid < 27) {
        float k = w3d[tid];
        w3p[2 * tid] = k; w3p[2 * tid + 1] = k;
    }

    // load halo tile via cp.async with zero-fill
    {
        unsigned dstb = s2u(xt);
        const float4* x4 = (const float4*)x;
        for (int i = tid; i < 5440; i += 256) {
            int w4 = i & 15, rest = i >> 4;
            int hi = rest % 10, ci = rest / 10;
            int cg = c0 - 1 + ci, hg = h0 - 1 + hi;
            bool ok = ((unsigned)cg < 512u) && ((unsigned)hg < 64u);
            const float4* src = ok ? (x4 + (((size_t)(b * 512 + cg) * 64 + hg) * 16 + w4)) : x4;
            int sz = ok ? 16 : 0;
            asm volatile("cp.async.cg.shared.global [%0], [%1], 16, %2;\n"
                         :: "r"(dstb + (unsigned)i * 16), "l"((const void*)src), "r"(sz));
        }
        asm volatile("cp.async.commit_group;\n" ::);
        asm volatile("cp.async.wait_group 0;\n" ::);
    }
    __syncthreads();

    int wg = tid & 7, hq = (tid >> 3) & 7, cq = tid >> 6;
    ull r[8][4];
#pragma unroll
    for (int i = 0; i < 8; i++)
#pragma unroll
        for (int p = 0; p < 4; p++) r[i][p] = 0ull;

#pragma unroll
    for (int dhi = 0; dhi < 3; dhi++) {
        ull wk[3][3];
#pragma unroll
        for (int dc = 0; dc < 3; dc++)
#pragma unroll
            for (int tp = 0; tp < 3; tp++)
                wk[dc][tp] = *(const ull*)(w3p + 2 * ((dc * 3 + dhi) * 3 + tp));
#pragma unroll
        for (int ii = 0; ii < 10; ii++) {
            const float* row = xt + ((cq * 8 + ii) * 10 + (hq + dhi)) * 64 + wg * 8;
            float4 m0 = *(const float4*)row;
            float4 m1 = *(const float4*)(row + 4);
            float left  = (wg == 0) ? 0.f : row[-1];
            float right = (wg == 7) ? 0.f : row[8];
            ull E0, E1, E2, E3, E4, O0, O1, O2, O3;
            PK2(E0, left, m0.x);  PK2(E1, m0.y, m0.z);
            PK2(E2, m0.w, m1.x);  PK2(E3, m1.y, m1.z);
            PK2(E4, m1.w, right);
            PK2(O0, m0.x, m0.y);  PK2(O1, m0.z, m0.w);
            PK2(O2, m1.x, m1.y);  PK2(O3, m1.z, m1.w);
#pragma unroll
            for (int dc = 0; dc < 3; dc++) {
                int cc = ii - dc;
                if (cc < 0 || cc > 7) continue;
                FMA2(r[cc][0], wk[dc][0], E0); FMA2(r[cc][0], wk[dc][1], O0); FMA2(r[cc][0], wk[dc][2], E1);
                FMA2(r[cc][1], wk[dc][0], E1); FMA2(r[cc][1], wk[dc][1], O1); FMA2(r[cc][1], wk[dc][2], E2);
                FMA2(r[cc][2], wk[dc][0], E2); FMA2(r[cc][2], wk[dc][1], O2); FMA2(r[cc][2], wk[dc][2], E3);
                FMA2(r[cc][3], wk[dc][0], E3); FMA2(r[cc][3], wk[dc][1], O3); FMA2(r[cc][3], wk[dc][2], E4);
            }
        }
    }

    // epilogue
    int h = h0 + hq;
    float inv[8];
    {
        float4 s0 = make_float4(0.f, 0.f, 0.f, 0.f), s1 = s0;
#pragma unroll
        for (int ct = 0; ct < 4; ct++) {
            const float4* pp = (const float4*)(g_psum +
                (((size_t)ct * 16 + b) * 64 + h) * 64 + wg * 8);
            float4 p0 = pp[0], p1 = pp[1];
            s0.x += p0.x; s0.y += p0.y; s0.z += p0.z; s0.w += p0.w;
            s1.x += p1.x; s1.y += p1.y; s1.z += p1.z; s1.w += p1.w;
        }
        inv[0] = 1.f / s0.x; inv[1] = 1.f / s0.y; inv[2] = 1.f / s0.z; inv[3] = 1.f / s0.w;
        inv[4] = 1.f / s1.x; inv[5] = 1.f / s1.y; inv[6] = 1.f / s1.z; inv[7] = 1.f / s1.w;
    }
#pragma unroll
    for (int cc = 0; cc < 8; cc++) {
        int c = c0 + cq * 8 + cc;
        const float* ctr = xt + ((cq * 8 + cc + 1) * 10 + (hq + 1)) * 64 + wg * 8;
        float4 xi0 = *(const float4*)ctr;
        float4 xi1 = *(const float4*)(ctr + 4);
        uint4 cv = *(const uint4*)(g_cp + ((size_t)(b * 512 + c) * 64 + h) * 64 + wg * 8);
        const __nv_bfloat162* cpp = (const __nv_bfloat162*)&cv;
        float xin[8] = {xi0.x, xi0.y, xi0.z, xi0.w, xi1.x, xi1.y, xi1.z, xi1.w};
        float o[8];
#pragma unroll
        for (int p = 0; p < 4; p++) {
            float lo, hi;
            UPK2(lo, hi, r[cc][p]);
            float2 cf = __bfloat1622float2(cpp[p]);
            o[2 * p]     = lo * (__expf(cf.x) * inv[2 * p])     + xin[2 * p];
            o[2 * p + 1] = hi * (__expf(cf.y) * inv[2 * p + 1]) + xin[2 * p + 1];
        }
        float* op = out + (((size_t)(b * 512 + c) * 64 + h) * 64 + wg * 8);
        *(float4*)(op)     = make_float4(o[0], o[1], o[2], o[3]);
        *(float4*)(op + 4) = make_float4(o[4], o[5], o[6], o[7]);
    }
}

// ---------------------------------------------------------------------------
extern "C" void kernel_launch(void* const* d_in, const int* in_sizes, int n_in,
                              void* d_out, int out_size) {
    const float* x   = (const float*)d_in[0];
    const float* w_c = (const float*)d_in[1];
    const float* a_c = (const float*)d_in[2];
    const float* w_w = (const float*)d_in[3];
    const float* a_w = (const float*)d_in[4];
    const float* w_h = (const float*)d_in[5];
    const float* a_h = (const float*)d_in[6];
    const float* w3d = (const float*)d_in[7];
    float* out = (float*)d_out;

    cudaFuncSetAttribute(k_gemmE, cudaFuncAttributeMaxDynamicSharedMemorySize, GE_BYTES);
    cudaFuncSetAttribute(k_conv, cudaFuncAttributeMaxDynamicSharedMemorySize, CV_BYTES);

    k_reduce<<<Bn * Cn, 256>>>(x);
    dim3 gridGap(Bn, 8, 2);
    k_gap<<<gridGap, 256>>>(0);
    k_branches<<<Bn, 256>>>(w_c, a_c, w_w, a_w, w_h, a_h);
    dim3 gridG(4, 16, Bn);
    k_gemmE<<<gridG, 256, GE_BYTES>>>(0);
    dim3 gridC(8, 16, Bn);
    k_conv<<<gridC, 256, CV_BYTES>>>(x, w3d, out);
}

// round 10
// speedup vs baseline: 1.2122x; 1.0443x over previous
#include <cuda_runtime.h>
#include <cuda_bf16.h>
#include <cstdint>

#define Bn 16
#define Cn 512
#define Hn 64
#define Wn 64
#define Rn 64
#define A_LD 72    // bf16 row stride for A (144B)
#define GB_LD 264  // bf16 row stride for B tile (528B = 33x16B, conflict-free)

typedef unsigned long long ull;

// Scratch (device globals; no allocation allowed)
__device__ float g_sumC[Bn*Cn];
__device__ float g_partW[Bn*Cn*Wn];
__device__ float g_partH[Bn*Cn*Hn];
__device__ float g_gap2[2*Bn*32*64];   // [sel][b][32 c-part][w]
__device__ __align__(16) __nv_bfloat16 g_cAb[Bn*Cn*A_LD];  // A[b][c][r] bf16
__device__ float g_wout[Bn*Rn*Wn];  // [b][r][w]
__device__ float g_hout[Bn*Rn*Hn];  // [b][r][h]
__device__ __align__(16) __nv_bfloat16 g_cp[(size_t)Bn*Cn*Hn*Wn];  // logits bf16
__device__ float g_psum[4*Bn*Hn*Wn];  // partial exp-sums [cT][b][h][w]

__device__ __forceinline__ unsigned s2u(const void* p) {
    return (unsigned)__cvta_generic_to_shared(p);
}

#define FMA2(d, a, bb) asm("fma.rn.f32x2 %0, %1, %2, %0;" : "+l"(d) : "l"(a), "l"(bb))
#define PK2(d, lo, hi) asm("mov.b64 %0, {%1, %2};" : "=l"(d) : "f"(lo), "f"(hi))
#define UPK2(lo, hi, v) asm("mov.b64 {%0, %1}, %2;" : "=f"(lo), "=f"(hi) : "l"(v))

// ---------------------------------------------------------------------------
// K1: per-(b,c) plane reductions
// ---------------------------------------------------------------------------
__global__ __launch_bounds__(256) void k_reduce(const float* __restrict__ x) {
    int plane = blockIdx.x;
    const float4* x4 = (const float4*)(x + (size_t)plane * 4096);
    int tid = threadIdx.x;

    __shared__ float4 s4[256];
    __shared__ float  sh[256][4];

    float4 wacc = make_float4(0.f, 0.f, 0.f, 0.f);
    float hacc[4];
#pragma unroll
    for (int k = 0; k < 4; k++) {
        float4 f = x4[tid + 256 * k];
        wacc.x += f.x; wacc.y += f.y; wacc.z += f.z; wacc.w += f.w;
        hacc[k] = f.x + f.y + f.z + f.w;
    }
    s4[tid] = wacc;
    sh[tid][0] = hacc[0]; sh[tid][1] = hacc[1];
    sh[tid][2] = hacc[2]; sh[tid][3] = hacc[3];
    __syncthreads();

    if (tid < 16) {
        float4 t = s4[tid];
#pragma unroll
        for (int j = 1; j < 16; j++) {
            float4 u = s4[tid + 16 * j];
            t.x += u.x; t.y += u.y; t.z += u.z; t.w += u.w;
        }
        ((float4*)g_partW)[plane * 16 + tid] = t;
        s4[tid] = t;
    }
    if (tid >= 64 && tid < 128) {
        int h = tid - 64;
        int base = (h & 15) * 16;
        int k = h >> 4;
        float s = 0.f;
#pragma unroll
        for (int j = 0; j < 16; j++) s += sh[base + j][k];
        g_partH[plane * 64 + h] = s;
    }
    __syncthreads();
    if (tid == 0) {
        float tot = 0.f;
#pragma unroll
        for (int j = 0; j < 16; j++) {
            float4 u = s4[j];
            tot += u.x + u.y + u.z + u.w;
        }
        g_sumC[plane] = tot;
    }
}

// ---------------------------------------------------------------------------
// K1b: parallel strided gap reductions
// ---------------------------------------------------------------------------
__global__ __launch_bounds__(256) void k_gap(int dummy) {
    int b = blockIdx.x, cq = blockIdx.y, sel = blockIdx.z;
    int tid = threadIdx.x;
    int w = tid & 63, cs = tid >> 6;
    const float* src = sel ? g_partH : g_partW;
    const float* p = src + ((size_t)(b * 512 + cq * 64 + cs * 16)) * 64 + w;
    float s = 0.f;
#pragma unroll
    for (int k = 0; k < 16; k++) s += p[k * 64];
    g_gap2[((size_t)(sel * 16 + b) * 32 + cq * 4 + cs) * 64 + w] = s;
}

// ---------------------------------------------------------------------------
// K2: finish gap means, 3-tap convs + PReLU
// ---------------------------------------------------------------------------
__global__ __launch_bounds__(256) void k_branches(
    const float* __restrict__ w_c, const float* __restrict__ a_c,
    const float* __restrict__ w_w, const float* __restrict__ a_w,
    const float* __restrict__ w_h, const float* __restrict__ a_h) {
    int b = blockIdx.x, tid = threadIdx.x;
    __shared__ float gc[Cn + 2];
    __shared__ float gw[Wn + 2];
    __shared__ float gh[Hn + 2];
    __shared__ float red[4][64];

    for (int i = tid; i < Cn; i += 256)
        gc[i + 1] = g_sumC[b * Cn + i] * (1.f / 4096.f);
    if (tid == 0) {
        gc[0] = 0.f; gc[Cn + 1] = 0.f;
        gw[0] = 0.f; gw[Wn + 1] = 0.f;
        gh[0] = 0.f; gh[Hn + 1] = 0.f;
    }
    {
        int q = tid >> 6, w = tid & 63;
        const float* p = g_gap2 + ((size_t)(b) * 32 + q * 8) * 64 + w;
        float s = 0.f;
#pragma unroll
        for (int j = 0; j < 8; j++) s += p[j * 64];
        red[q][w] = s;
    }
    __syncthreads();
    if (tid < 64)
        gw[tid + 1] = (red[0][tid] + red[1][tid] + red[2][tid] + red[3][tid]) * (1.f / 32768.f);
    __syncthreads();
    {
        int q = tid >> 6, w = tid & 63;
        const float* p = g_gap2 + ((size_t)(16 + b) * 32 + q * 8) * 64 + w;
        float s = 0.f;
#pragma unroll
        for (int j = 0; j < 8; j++) s += p[j * 64];
        red[q][w] = s;
    }
    __syncthreads();
    if (tid < 64)
        gh[tid + 1] = (red[0][tid] + red[1][tid] + red[2][tid] + red[3][tid]) * (1.f / 32768.f);
    __syncthreads();

    float acv = a_c[0], awv = a_w[0], ahv = a_h[0];
    for (int i = tid; i < Rn * Cn; i += 256) {
        int r = i >> 9, c = i & 511;
        float v = w_c[r * 3] * gc[c] + w_c[r * 3 + 1] * gc[c + 1] + w_c[r * 3 + 2] * gc[c + 2];
        v = (v >= 0.f) ? v : acv * v;
        g_cAb[((size_t)(b * Cn + c)) * A_LD + r] = __float2bfloat16(v);
    }
    for (int i = tid; i < Rn * Wn; i += 256) {
        int r = i >> 6, w = i & 63;
        float v = w_w[r * 3] * gw[w] + w_w[r * 3 + 1] * gw[w + 1] + w_w[r * 3 + 2] * gw[w + 2];
        g_wout[b * Rn * Wn + i] = (v >= 0.f) ? v : awv * v;
        float v2 = w_h[r * 3] * gh[w] + w_h[r * 3 + 1] * gh[w + 1] + w_h[r * 3 + 2] * gh[w + 2];
        g_hout[b * Rn * Hn + i] = (v2 >= 0.f) ? v2 : ahv * v2;
    }
}

// ---------------------------------------------------------------------------
// K3a v4: like v3 but cp staged in smem (dead A region) -> coalesced stores.
// ---------------------------------------------------------------------------
#define GE_A    0        // bf16 [128][A_LD] = 18432 (A, then cp staging)
#define GE_B    18432    // bf16 [64][GB_LD] = 33792
#define GE_WO   52224    // f32 [64][64] = 16384 ; reused as wred
#define GE_HO   68608    // f32 [64][4]  = 1024
#define GE_BYTES 69632

__global__ void __launch_bounds__(256) k_gemmE(int dummy) {
    extern __shared__ char sm[];
    int cT = blockIdx.x, h0 = blockIdx.y * 4, b = blockIdx.z;
    int tid = threadIdx.x;
    int lane = tid & 31, wid = tid >> 5;

    float* wo_s = (float*)(sm + GE_WO);
    float* ho_s = (float*)(sm + GE_HO);

    // stage A, wo, ho
    {
        const uint4* src = (const uint4*)(g_cAb + ((size_t)b * 512 + cT * 128) * A_LD);
        uint4* dst = (uint4*)(sm + GE_A);
        for (int i = tid; i < 1152; i += 256) dst[i] = src[i];
        const float4* wsrc = (const float4*)(g_wout + (size_t)b * 4096);
        float4* wdst = (float4*)wo_s;
        for (int i = tid; i < 1024; i += 256) wdst[i] = wsrc[i];
        int r = tid >> 2, hh = tid & 3;
        ho_s[tid] = g_hout[(size_t)b * 4096 + r * 64 + h0 + hh];
    }
    __syncthreads();

    // hoist A fragments (A smem dead afterwards)
    unsigned afr[4][4];
    {
        unsigned aBase = s2u(sm + GE_A);
        int cb = wid * 16;
        int aRow = lane & 15;
        unsigned aColOff = (unsigned)(lane >> 4) * 16u;
#pragma unroll
        for (int ks = 0; ks < 4; ks++) {
            unsigned ad = aBase + (unsigned)((cb + aRow) * A_LD + ks * 16) * 2u + aColOff;
            asm volatile("ldmatrix.sync.aligned.m8n8.x4.shared.b16 {%0,%1,%2,%3}, [%4];\n"
                         : "=r"(afr[ks][0]), "=r"(afr[ks][1]),
                           "=r"(afr[ks][2]), "=r"(afr[ks][3])
                         : "r"(ad));
        }
    }

    // build B once: B[r][hj*64+w] = ho[r][hj] * wo[r][w]
    {
        __nv_bfloat16* B = (__nv_bfloat16*)(sm + GE_B);
        for (int i = tid; i < 8192; i += 256) {
            int r = i >> 7, col = (i & 127) * 2;
            int hj = col >> 6, w = col & 63;
            float hv = ho_s[r * 4 + hj];
            *(__nv_bfloat162*)(B + r * GB_LD + col) =
                __floats2bfloat162_rn(hv * wo_s[r * 64 + w], hv * wo_s[r * 64 + w + 1]);
        }
    }
    __syncthreads();

    float* wred = wo_s;  // reuse (wo dead after B build)
    unsigned sBase = s2u(sm + GE_B);
    int bRowOff = (lane & 7) + ((lane & 8) ? 8 : 0);
    int bColOff = (lane & 16) ? 8 : 0;

    for (int hj = 0; hj < 4; hj++) {
        int h = h0 + hj;
        float acc[8][4];
#pragma unroll
        for (int t = 0; t < 8; t++)
#pragma unroll
            for (int q = 0; q < 4; q++) acc[t][q] = 0.f;

#pragma unroll
        for (int ks = 0; ks < 4; ks++) {
            int k0 = ks * 16;
#pragma unroll
            for (int nb = 0; nb < 4; nb++) {
                unsigned bd = sBase +
                    (unsigned)((k0 + bRowOff) * GB_LD + hj * 64 + nb * 16 + bColOff) * 2u;
                unsigned bq0, bq1, bq2, bq3;
                asm volatile("ldmatrix.sync.aligned.m8n8.x4.trans.shared.b16 {%0,%1,%2,%3}, [%4];\n"
                             : "=r"(bq0), "=r"(bq1), "=r"(bq2), "=r"(bq3) : "r"(bd));
                asm volatile(
                    "mma.sync.aligned.m16n8k16.row.col.f32.bf16.bf16.f32 "
                    "{%0,%1,%2,%3},{%4,%5,%6,%7},{%8,%9},{%0,%1,%2,%3};\n"
                    : "+f"(acc[2 * nb][0]), "+f"(acc[2 * nb][1]),
                      "+f"(acc[2 * nb][2]), "+f"(acc[2 * nb][3])
                    : "r"(afr[ks][0]), "r"(afr[ks][1]), "r"(afr[ks][2]), "r"(afr[ks][3]),
                      "r"(bq0), "r"(bq1));
                asm volatile(
                    "mma.sync.aligned.m16n8k16.row.col.f32.bf16.bf16.f32 "
                    "{%0,%1,%2,%3},{%4,%5,%6,%7},{%8,%9},{%0,%1,%2,%3};\n"
                    : "+f"(acc[2 * nb + 1][0]), "+f"(acc[2 * nb + 1][1]),
                      "+f"(acc[2 * nb + 1][2]), "+f"(acc[2 * nb + 1][3])
                    : "r"(afr[ks][0]), "r"(afr[ks][1]), "r"(afr[ks][2]), "r"(afr[ks][3]),
                      "r"(bq2), "r"(bq3));
            }
        }

        // stage cp tile into dead A region (conflict-free: 144B row stride)
        {
            int c_loc = wid * 16 + (lane >> 2);
#pragma unroll
            for (int t = 0; t < 8; t++) {
                int w = t * 8 + (lane & 3) * 2;
                *(__nv_bfloat162*)(sm + GE_A + c_loc * 144 + w * 2) =
                    __floats2bfloat162_rn(acc[t][0], acc[t][1]);
                *(__nv_bfloat162*)(sm + GE_A + (c_loc + 8) * 144 + w * 2) =
                    __floats2bfloat162_rn(acc[t][2], acc[t][3]);
                float sA = __expf(acc[t][0]) + __expf(acc[t][2]);
                float sB = __expf(acc[t][1]) + __expf(acc[t][3]);
                sA += __shfl_xor_sync(0xffffffffu, sA, 4);
                sB += __shfl_xor_sync(0xffffffffu, sB, 4);
                sA += __shfl_xor_sync(0xffffffffu, sA, 8);
                sB += __shfl_xor_sync(0xffffffffu, sB, 8);
                sA += __shfl_xor_sync(0xffffffffu, sA, 16);
                sB += __shfl_xor_sync(0xffffffffu, sB, 16);
                if (lane < 4) {
                    wred[(hj * 8 + wid) * 64 + w]     = sA;
                    wred[(hj * 8 + wid) * 64 + w + 1] = sB;
                }
            }
        }
        __syncthreads();
        // coalesced cp write: 128 c-rows x 128B
        {
            int cbase = cT * 128;
            for (int i = tid; i < 1024; i += 256) {
                int c = i >> 3, q = i & 7;
                uint4 v = *(const uint4*)(sm + GE_A + c * 144 + q * 16);
                *((uint4*)(g_cp + ((size_t)(b * 512 + cbase + c) * 64 + h) * 64) + q) = v;
            }
        }
        __syncthreads();
    }

    // final psum reduce: 256 threads = 4 h x 64 w
    {
        int hj = tid >> 6, w = tid & 63;
        float s = 0.f;
#pragma unroll
        for (int k = 0; k < 8; k++) s += wred[(hj * 8 + k) * 64 + w];
        g_psum[(((size_t)cT * 16 + b) * 64 + h0 + hj) * 64 + w] = s;
    }
}

// ---------------------------------------------------------------------------
// K3b v3: resident double-buffered streaming conv.
// Block = (8-h tile, c-half, b) = 256 blocks, 256 thr, 2 CTAs/SM, 16 chunks.
// ---------------------------------------------------------------------------
#define CV_TILE_F (18 * 10 * 64)               // 11520 floats = 46080 B
#define CV_BYTES  (2 * CV_TILE_F * 4 + 256)    // 92416

__global__ void __launch_bounds__(256, 2) k_conv(
    const float* __restrict__ x, const float* __restrict__ w3d,
    float* __restrict__ out) {
    extern __shared__ float smc[];
    float* w3p = smc + 2 * CV_TILE_F;   // 27 packed (k,k) pairs
    int h0 = blockIdx.x * 8;
    int half = blockIdx.y;
    int b = blockIdx.z;
    int tid = threadIdx.x;

    if (tid < 27) {
        float k = w3d[tid];
        w3p[2 * tid] = k; w3p[2 * tid + 1] = k;
    }

    int wg = tid & 7, hq = (tid >> 3) & 7, cq = tid >> 6;  // 4 c per thread
    int h = h0 + hq;

    // stage chunk ch (18 c-planes x 10 h x 64 w) into buffer ch&1
    auto stage = [&](int ch) {
        float* buf = smc + (ch & 1) * CV_TILE_F;
        unsigned dstb = s2u(buf);
        int c0 = half * 256 + ch * 16;
        const float4* x4 = (const float4*)x;
        for (int i = tid; i < 2880; i += 256) {
            int w4 = i & 15, rest = i >> 4;
            int hi = rest % 10, ci = rest / 10;
            int cg = c0 - 1 + ci, hg = h0 - 1 + hi;
            bool ok = ((unsigned)cg < 512u) && ((unsigned)hg < 64u);
            const float4* src = ok ? (x4 + (((size_t)(b * 512 + cg) * 64 + hg) * 16 + w4)) : x4;
            int sz = ok ? 16 : 0;
            asm volatile("cp.async.cg.shared.global [%0], [%1], 16, %2;\n"
                         :: "r"(dstb + (unsigned)i * 16), "l"((const void*)src), "r"(sz));
        }
        asm volatile("cp.async.commit_group;\n" ::);
    };

    // hoist softmax denominators (fixed h,w per thread)
    float inv[8];
    {
        float4 s0 = make_float4(0.f, 0.f, 0.f, 0.f), s1 = s0;
#pragma unroll
        for (int ct = 0; ct < 4; ct++) {
            const float4* pp = (const float4*)(g_psum +
                (((size_t)ct * 16 + b) * 64 + h) * 64 + wg * 8);
            float4 p0 = pp[0], p1 = pp[1];
            s0.x += p0.x; s0.y += p0.y; s0.z += p0.z; s0.w += p0.w;
            s1.x += p1.x; s1.y += p1.y; s1.z += p1.z; s1.w += p1.w;
        }
        inv[0] = 1.f / s0.x; inv[1] = 1.f / s0.y; inv[2] = 1.f / s0.z; inv[3] = 1.f / s0.w;
        inv[4] = 1.f / s1.x; inv[5] = 1.f / s1.y; inv[6] = 1.f / s1.z; inv[7] = 1.f / s1.w;
    }

    stage(0);
    for (int ch = 0; ch < 16; ch++) {
        if (ch < 15) {
            stage(ch + 1);
            asm volatile("cp.async.wait_group 1;\n" ::);
        } else {
            asm volatile("cp.async.wait_group 0;\n" ::);
        }
        __syncthreads();
        const float* buf = smc + (ch & 1) * CV_TILE_F;

        ull r[4][4];
#pragma unroll
        for (int i = 0; i < 4; i++)
#pragma unroll
            for (int p = 0; p < 4; p++) r[i][p] = 0ull;

#pragma unroll
        for (int dhi = 0; dhi < 3; dhi++) {
            ull wk[3][3];
#pragma unroll
            for (int dc = 0; dc < 3; dc++)
#pragma unroll
                for (int tp = 0; tp < 3; tp++)
                    wk[dc][tp] = *(const ull*)(w3p + 2 * ((dc * 3 + dhi) * 3 + tp));
#pragma unroll
            for (int p = 0; p < 6; p++) {   // local input plane cq*4 + p
                const float* row = buf + ((cq * 4 + p) * 10 + (hq + dhi)) * 64 + wg * 8;
                float4 m0 = *(const float4*)row;
                float4 m1 = *(const float4*)(row + 4);
                float left  = (wg == 0) ? 0.f : row[-1];
                float right = (wg == 7) ? 0.f : row[8];
                ull E0, E1, E2, E3, E4, O0, O1, O2, O3;
                PK2(E0, left, m0.x);  PK2(E1, m0.y, m0.z);
                PK2(E2, m0.w, m1.x);  PK2(E3, m1.y, m1.z);
                PK2(E4, m1.w, right);
                PK2(O0, m0.x, m0.y);  PK2(O1, m0.z, m0.w);
                PK2(O2, m1.x, m1.y);  PK2(O3, m1.z, m1.w);
#pragma unroll
                for (int dc = 0; dc < 3; dc++) {
                    int cc = p - dc;
                    if (cc < 0 || cc > 3) continue;
                    FMA2(r[cc][0], wk[dc][0], E0); FMA2(r[cc][0], wk[dc][1], O0); FMA2(r[cc][0], wk[dc][2], E1);
                    FMA2(r[cc][1], wk[dc][0], E1); FMA2(r[cc][1], wk[dc][1], O1); FMA2(r[cc][1], wk[dc][2], E2);
                    FMA2(r[cc][2], wk[dc][0], E2); FMA2(r[cc][2], wk[dc][1], O2); FMA2(r[cc][2], wk[dc][2], E3);
                    FMA2(r[cc][3], wk[dc][0], E3); FMA2(r[cc][3], wk[dc][1], O3); FMA2(r[cc][3], wk[dc][2], E4);
                }
            }
        }

        // epilogue for this chunk
        int c0 = half * 256 + ch * 16;
#pragma unroll
        for (int cc = 0; cc < 4; cc++) {
            int c = c0 + cq * 4 + cc;
            const float* ctr = buf + ((cq * 4 + cc + 1) * 10 + (hq + 1)) * 64 + wg * 8;
            float4 xi0 = *(const float4*)ctr;
            float4 xi1 = *(const float4*)(ctr + 4);
            uint4 cv = *(const uint4*)(g_cp + ((size_t)(b * 512 + c) * 64 + h) * 64 + wg * 8);
            const __nv_bfloat162* cpp = (const __nv_bfloat162*)&cv;
            float xin[8] = {xi0.x, xi0.y, xi0.z, xi0.w, xi1.x, xi1.y, xi1.z, xi1.w};
            float o[8];
#pragma unroll
            for (int p = 0; p < 4; p++) {
                float lo, hi;
                UPK2(lo, hi, r[cc][p]);
                float2 cf = __bfloat1622float2(cpp[p]);
                o[2 * p]     = lo * (__expf(cf.x) * inv[2 * p])     + xin[2 * p];
                o[2 * p + 1] = hi * (__expf(cf.y) * inv[2 * p + 1]) + xin[2 * p + 1];
            }
            float* op = out + (((size_t)(b * 512 + c) * 64 + h) * 64 + wg * 8);
            *(float4*)(op)     = make_float4(o[0], o[1], o[2], o[3]);
            *(float4*)(op + 4) = make_float4(o[4], o[5], o[6], o[7]);
        }
        __syncthreads();   // buffer reuse guard before next prefetch
    }
}

// ---------------------------------------------------------------------------
extern "C" void kernel_launch(void* const* d_in, const int* in_sizes, int n_in,
                              void* d_out, int out_size) {
    const float* x   = (const float*)d_in[0];
    const float* w_c = (const float*)d_in[1];
    const float* a_c = (const float*)d_in[2];
    const float* w_w = (const float*)d_in[3];
    const float* a_w = (const float*)d_in[4];
    const float* w_h = (const float*)d_in[5];
    const float* a_h = (const float*)d_in[6];
    const float* w3d = (const float*)d_in[7];
    float* out = (float*)d_out;

    cudaFuncSetAttribute(k_gemmE, cudaFuncAttributeMaxDynamicSharedMemorySize, GE_BYTES);
    cudaFuncSetAttribute(k_conv, cudaFuncAttributeMaxDynamicSharedMemorySize, CV_BYTES);

    k_reduce<<<Bn * Cn, 256>>>(x);
    dim3 gridGap(Bn, 8, 2);
    k_gap<<<gridGap, 256>>>(0);
    k_branches<<<Bn, 256>>>(w_c, a_c, w_w, a_w, w_h, a_h);
    dim3 gridG(4, 16, Bn);
    k_gemmE<<<gridG, 256, GE_BYTES>>>(0);
    dim3 gridC(8, 2, Bn);
    k_conv<<<gridC, 256, CV_BYTES>>>(x, w3d, out);
}

// round 11
// speedup vs baseline: 1.3376x; 1.1034x over previous
#include <cuda_runtime.h>
#include <cuda_bf16.h>
#include <cstdint>

#define Bn 16
#define Cn 512
#define Hn 64
#define Wn 64
#define Rn 64
#define A_LD 72    // bf16 row stride for A (144B)
#define GB_LD 264  // bf16 row stride for B tile (528B = 33x16B, conflict-free)

typedef unsigned long long ull;

// Scratch (device globals; no allocation allowed)
__device__ float g_sumC[Bn*Cn];
__device__ float g_partW[Bn*Cn*Wn];
__device__ float g_partH[Bn*Cn*Hn];
__device__ float g_wout[Bn*Rn*Wn];  // [b][r][w]
__device__ float g_hout[Bn*Rn*Hn];  // [b][r][h]
__device__ __align__(16) __nv_bfloat16 g_cp[(size_t)Bn*Cn*Hn*Wn];  // logits bf16
__device__ float g_psum[4*Bn*Hn*Wn];  // partial exp-sums [cT][b][h][w]

__device__ __forceinline__ unsigned s2u(const void* p) {
    return (unsigned)__cvta_generic_to_shared(p);
}

#define FMA2(d, a, bb) asm("fma.rn.f32x2 %0, %1, %2, %0;" : "+l"(d) : "l"(a), "l"(bb))
#define PK2(d, lo, hi) asm("mov.b64 %0, {%1, %2};" : "=l"(d) : "f"(lo), "f"(hi))
#define UPK2(lo, hi, v) asm("mov.b64 {%0, %1}, %2;" : "=f"(lo), "=f"(hi) : "l"(v))

// ---------------------------------------------------------------------------
// K1: per-(b,c) plane reductions
// ---------------------------------------------------------------------------
__global__ __launch_bounds__(256) void k_reduce(const float* __restrict__ x) {
    int plane = blockIdx.x;
    const float4* x4 = (const float4*)(x + (size_t)plane * 4096);
    int tid = threadIdx.x;

    __shared__ float4 s4[256];
    __shared__ float  sh[256][4];

    float4 wacc = make_float4(0.f, 0.f, 0.f, 0.f);
    float hacc[4];
#pragma unroll
    for (int k = 0; k < 4; k++) {
        float4 f = x4[tid + 256 * k];
        wacc.x += f.x; wacc.y += f.y; wacc.z += f.z; wacc.w += f.w;
        hacc[k] = f.x + f.y + f.z + f.w;
    }
    s4[tid] = wacc;
    sh[tid][0] = hacc[0]; sh[tid][1] = hacc[1];
    sh[tid][2] = hacc[2]; sh[tid][3] = hacc[3];
    __syncthreads();

    if (tid < 16) {
        float4 t = s4[tid];
#pragma unroll
        for (int j = 1; j < 16; j++) {
            float4 u = s4[tid + 16 * j];
            t.x += u.x; t.y += u.y; t.z += u.z; t.w += u.w;
        }
        ((float4*)g_partW)[plane * 16 + tid] = t;
        s4[tid] = t;
    }
    if (tid >= 64 && tid < 128) {
        int h = tid - 64;
        int base = (h & 15) * 16;
        int k = h >> 4;
        float s = 0.f;
#pragma unroll
        for (int j = 0; j < 16; j++) s += sh[base + j][k];
        g_partH[plane * 64 + h] = s;
    }
    __syncthreads();
    if (tid == 0) {
        float tot = 0.f;
#pragma unroll
        for (int j = 0; j < 16; j++) {
            float4 u = s4[j];
            tot += u.x + u.y + u.z + u.w;
        }
        g_sumC[plane] = tot;
    }
}

// ---------------------------------------------------------------------------
// K2: gap reductions + 3-tap branch conv + PReLU -> g_wout / g_hout.
// grid (16 b, 2 sel), 256 thr.
// ---------------------------------------------------------------------------
__global__ __launch_bounds__(256) void k_gap2(
    const float* __restrict__ w_w, const float* __restrict__ a_w,
    const float* __restrict__ w_h, const float* __restrict__ a_h) {
    int b = blockIdx.x, sel = blockIdx.y;
    int tid = threadIdx.x;
    int w = tid & 63, part = tid >> 6;

    __shared__ float red[4][64];
    __shared__ float g[66];

    const float* src = sel ? g_partH : g_partW;
    const float* p = src + ((size_t)(b * 512 + part * 128)) * 64 + w;
    float s = 0.f;
#pragma unroll 8
    for (int c = 0; c < 128; c++) s += p[c * 64];
    red[part][w] = s;
    if (tid == 64 + 0) g[0] = 0.f;
    if (tid == 64 + 1) g[65] = 0.f;
    __syncthreads();
    if (tid < 64)
        g[tid + 1] = (red[0][tid] + red[1][tid] + red[2][tid] + red[3][tid]) * (1.f / 32768.f);
    __syncthreads();

    const float* wt = sel ? w_h : w_w;
    float av = sel ? a_h[0] : a_w[0];
    float* dst = (sel ? g_hout : g_wout) + (size_t)b * 4096;
    for (int i = tid; i < 4096; i += 256) {
        int r = i >> 6, w2 = i & 63;
        float v = wt[r * 3] * g[w2] + wt[r * 3 + 1] * g[w2 + 1] + wt[r * 3 + 2] * g[w2 + 2];
        dst[i] = (v >= 0.f) ? v : av * v;
    }
}

// ---------------------------------------------------------------------------
// K3: tiled MMA (A built in-block from g_sumC + w_c), cp smem-staged ->
// coalesced stores, partial exp-sums.
// ---------------------------------------------------------------------------
#define GE_A    0        // bf16 [128][A_LD] = 18432 (A, then cp staging)
#define GE_B    18432    // bf16 [64][GB_LD] = 33792
#define GE_WO   52224    // f32 [64][64] = 16384 ; reused as wred
#define GE_HO   68608    // f32 [64][4]  = 1024
#define GE_GC   69632    // f32 [132]
#define GE_WC   70160    // f32 [192]
#define GE_BYTES 71168

__global__ void __launch_bounds__(256) k_gemmE(
    const float* __restrict__ w_c, const float* __restrict__ a_c) {
    extern __shared__ char sm[];
    int cT = blockIdx.x, h0 = blockIdx.y * 4, b = blockIdx.z;
    int tid = threadIdx.x;
    int lane = tid & 31, wid = tid >> 5;

    float* wo_s = (float*)(sm + GE_WO);
    float* ho_s = (float*)(sm + GE_HO);
    float* gcs  = (float*)(sm + GE_GC);
    float* wcs  = (float*)(sm + GE_WC);

    // stage gc slice, channel weights, wo, ho
    {
        const float* sumC = g_sumC + b * 512;
        for (int i = tid; i < 130; i += 256) {
            int cg = cT * 128 - 1 + i;
            gcs[i] = ((unsigned)cg < 512u) ? sumC[cg] * (1.f / 4096.f) : 0.f;
        }
        if (tid < 192) wcs[tid] = w_c[tid];
        const float4* wsrc = (const float4*)(g_wout + (size_t)b * 4096);
        float4* wdst = (float4*)wo_s;
        for (int i = tid; i < 1024; i += 256) wdst[i] = wsrc[i];
        int r = tid >> 2, hh = tid & 3;
        ho_s[tid] = g_hout[(size_t)b * 4096 + r * 64 + h0 + hh];
    }
    __syncthreads();

    // build A tile bf16 [128 c][64 r] with PReLU
    {
        float av = a_c[0];
        __nv_bfloat16* A = (__nv_bfloat16*)(sm + GE_A);
        for (int i = tid; i < 4096; i += 256) {
            int c = i >> 5, r2 = (i & 31) * 2;
            float g0 = gcs[c], g1 = gcs[c + 1], g2 = gcs[c + 2];
            float v0 = wcs[r2 * 3] * g0 + wcs[r2 * 3 + 1] * g1 + wcs[r2 * 3 + 2] * g2;
            float v1 = wcs[r2 * 3 + 3] * g0 + wcs[r2 * 3 + 4] * g1 + wcs[r2 * 3 + 5] * g2;
            v0 = (v0 >= 0.f) ? v0 : av * v0;
            v1 = (v1 >= 0.f) ? v1 : av * v1;
            *(__nv_bfloat162*)(A + c * A_LD + r2) = __floats2bfloat162_rn(v0, v1);
        }
    }
    __syncthreads();

    // hoist A fragments (A smem dead afterwards)
    unsigned afr[4][4];
    {
        unsigned aBase = s2u(sm + GE_A);
        int cb = wid * 16;
        int aRow = lane & 15;
        unsigned aColOff = (unsigned)(lane >> 4) * 16u;
#pragma unroll
        for (int ks = 0; ks < 4; ks++) {
            unsigned ad = aBase + (unsigned)((cb + aRow) * A_LD + ks * 16) * 2u + aColOff;
            asm volatile("ldmatrix.sync.aligned.m8n8.x4.shared.b16 {%0,%1,%2,%3}, [%4];\n"
                         : "=r"(afr[ks][0]), "=r"(afr[ks][1]),
                           "=r"(afr[ks][2]), "=r"(afr[ks][3])
                         : "r"(ad));
        }
    }

    // build B once: B[r][hj*64+w] = ho[r][hj] * wo[r][w]
    {
        __nv_bfloat16* B = (__nv_bfloat16*)(sm + GE_B);
        for (int i = tid; i < 8192; i += 256) {
            int r = i >> 7, col = (i & 127) * 2;
            int hj = col >> 6, w = col & 63;
            float hv = ho_s[r * 4 + hj];
            *(__nv_bfloat162*)(B + r * GB_LD + col) =
                __floats2bfloat162_rn(hv * wo_s[r * 64 + w], hv * wo_s[r * 64 + w + 1]);
        }
    }
    __syncthreads();

    float* wred = wo_s;  // reuse (wo dead after B build)
    unsigned sBase = s2u(sm + GE_B);
    int bRowOff = (lane & 7) + ((lane & 8) ? 8 : 0);
    int bColOff = (lane & 16) ? 8 : 0;

    for (int hj = 0; hj < 4; hj++) {
        int h = h0 + hj;
        float acc[8][4];
#pragma unroll
        for (int t = 0; t < 8; t++)
#pragma unroll
            for (int q = 0; q < 4; q++) acc[t][q] = 0.f;

#pragma unroll
        for (int ks = 0; ks < 4; ks++) {
            int k0 = ks * 16;
#pragma unroll
            for (int nb = 0; nb < 4; nb++) {
                unsigned bd = sBase +
                    (unsigned)((k0 + bRowOff) * GB_LD + hj * 64 + nb * 16 + bColOff) * 2u;
                unsigned bq0, bq1, bq2, bq3;
                asm volatile("ldmatrix.sync.aligned.m8n8.x4.trans.shared.b16 {%0,%1,%2,%3}, [%4];\n"
                             : "=r"(bq0), "=r"(bq1), "=r"(bq2), "=r"(bq3) : "r"(bd));
                asm volatile(
                    "mma.sync.aligned.m16n8k16.row.col.f32.bf16.bf16.f32 "
                    "{%0,%1,%2,%3},{%4,%5,%6,%7},{%8,%9},{%0,%1,%2,%3};\n"
                    : "+f"(acc[2 * nb][0]), "+f"(acc[2 * nb][1]),
                      "+f"(acc[2 * nb][2]), "+f"(acc[2 * nb][3])
                    : "r"(afr[ks][0]), "r"(afr[ks][1]), "r"(afr[ks][2]), "r"(afr[ks][3]),
                      "r"(bq0), "r"(bq1));
                asm volatile(
                    "mma.sync.aligned.m16n8k16.row.col.f32.bf16.bf16.f32 "
                    "{%0,%1,%2,%3},{%4,%5,%6,%7},{%8,%9},{%0,%1,%2,%3};\n"
                    : "+f"(acc[2 * nb + 1][0]), "+f"(acc[2 * nb + 1][1]),
                      "+f"(acc[2 * nb + 1][2]), "+f"(acc[2 * nb + 1][3])
                    : "r"(afr[ks][0]), "r"(afr[ks][1]), "r"(afr[ks][2]), "r"(afr[ks][3]),
                      "r"(bq2), "r"(bq3));
            }
        }

        // stage cp tile into dead A region (144B row stride)
        {
            int c_loc = wid * 16 + (lane >> 2);
#pragma unroll
            for (int t = 0; t < 8; t++) {
                int w = t * 8 + (lane & 3) * 2;
                *(__nv_bfloat162*)(sm + GE_A + c_loc * 144 + w * 2) =
                    __floats2bfloat162_rn(acc[t][0], acc[t][1]);
                *(__nv_bfloat162*)(sm + GE_A + (c_loc + 8) * 144 + w * 2) =
                    __floats2bfloat162_rn(acc[t][2], acc[t][3]);
                float sA = __expf(acc[t][0]) + __expf(acc[t][2]);
                float sB = __expf(acc[t][1]) + __expf(acc[t][3]);
                sA += __shfl_xor_sync(0xffffffffu, sA, 4);
                sB += __shfl_xor_sync(0xffffffffu, sB, 4);
                sA += __shfl_xor_sync(0xffffffffu, sA, 8);
                sB += __shfl_xor_sync(0xffffffffu, sB, 8);
                sA += __shfl_xor_sync(0xffffffffu, sA, 16);
                sB += __shfl_xor_sync(0xffffffffu, sB, 16);
                if (lane < 4) {
                    wred[(hj * 8 + wid) * 64 + w]     = sA;
                    wred[(hj * 8 + wid) * 64 + w + 1] = sB;
                }
            }
        }
        __syncthreads();
        // coalesced cp write: 128 c-rows x 128B
        {
            int cbase = cT * 128;
            for (int i = tid; i < 1024; i += 256) {
                int c = i >> 3, q = i & 7;
                uint4 v = *(const uint4*)(sm + GE_A + c * 144 + q * 16);
                *((uint4*)(g_cp + ((size_t)(b * 512 + cbase + c) * 64 + h) * 64) + q) = v;
            }
        }
        __syncthreads();
    }

    // final psum reduce: 256 threads = 4 h x 64 w
    {
        int hj = tid >> 6, w = tid & 63;
        float s = 0.f;
#pragma unroll
        for (int k = 0; k < 8; k++) s += wred[(hj * 8 + k) * 64 + w];
        g_psum[(((size_t)cT * 16 + b) * 64 + h0 + hj) * 64 + w] = s;
    }
}

// ---------------------------------------------------------------------------
// K4: resident double-buffered streaming conv.
// Block = (8-h tile, c-quarter, b) = 512 blocks, 256 thr, 2 CTAs/SM, 8 chunks.
// ---------------------------------------------------------------------------
#define CV_TILE_F (18 * 10 * 64)               // 11520 floats = 46080 B
#define CV_BYTES  (2 * CV_TILE_F * 4 + 256)    // 92416

__global__ void __launch_bounds__(256, 2) k_conv(
    const float* __restrict__ x, const float* __restrict__ w3d,
    float* __restrict__ out) {
    extern __shared__ float smc[];
    float* w3p = smc + 2 * CV_TILE_F;   // 27 packed (k,k) pairs
    int h0 = blockIdx.x * 8;
    int quarter = blockIdx.y;
    int b = blockIdx.z;
    int tid = threadIdx.x;

    if (tid < 27) {
        float k = w3d[tid];
        w3p[2 * tid] = k; w3p[2 * tid + 1] = k;
    }

    int wg = tid & 7, hq = (tid >> 3) & 7, cq = tid >> 6;  // 4 c per thread
    int h = h0 + hq;

    // stage chunk ch (18 c-planes x 10 h x 64 w) into buffer ch&1
    auto stage = [&](int ch) {
        float* buf = smc + (ch & 1) * CV_TILE_F;
        unsigned dstb = s2u(buf);
        int c0 = quarter * 128 + ch * 16;
        const float4* x4 = (const float4*)x;
        for (int i = tid; i < 2880; i += 256) {
            int w4 = i & 15, rest = i >> 4;
            int hi = rest % 10, ci = rest / 10;
            int cg = c0 - 1 + ci, hg = h0 - 1 + hi;
            bool ok = ((unsigned)cg < 512u) && ((unsigned)hg < 64u);
            const float4* src = ok ? (x4 + (((size_t)(b * 512 + cg) * 64 + hg) * 16 + w4)) : x4;
            int sz = ok ? 16 : 0;
            asm volatile("cp.async.cg.shared.global [%0], [%1], 16, %2;\n"
                         :: "r"(dstb + (unsigned)i * 16), "l"((const void*)src), "r"(sz));
        }
        asm volatile("cp.async.commit_group;\n" ::);
    };

    // hoist softmax denominators (fixed h,w per thread)
    float inv[8];
    {
        float4 s0 = make_float4(0.f, 0.f, 0.f, 0.f), s1 = s0;
#pragma unroll
        for (int ct = 0; ct < 4; ct++) {
            const float4* pp = (const float4*)(g_psum +
                (((size_t)ct * 16 + b) * 64 + h) * 64 + wg * 8);
            float4 p0 = pp[0], p1 = pp[1];
            s0.x += p0.x; s0.y += p0.y; s0.z += p0.z; s0.w += p0.w;
            s1.x += p1.x; s1.y += p1.y; s1.z += p1.z; s1.w += p1.w;
        }
        inv[0] = 1.f / s0.x; inv[1] = 1.f / s0.y; inv[2] = 1.f / s0.z; inv[3] = 1.f / s0.w;
        inv[4] = 1.f / s1.x; inv[5] = 1.f / s1.y; inv[6] = 1.f / s1.z; inv[7] = 1.f / s1.w;
    }

    stage(0);
    for (int ch = 0; ch < 8; ch++) {
        if (ch < 7) {
            stage(ch + 1);
            asm volatile("cp.async.wait_group 1;\n" ::);
        } else {
            asm volatile("cp.async.wait_group 0;\n" ::);
        }
        __syncthreads();
        const float* buf = smc + (ch & 1) * CV_TILE_F;

        ull r[4][4];
#pragma unroll
        for (int i = 0; i < 4; i++)
#pragma unroll
            for (int p = 0; p < 4; p++) r[i][p] = 0ull;

#pragma unroll
        for (int dhi = 0; dhi < 3; dhi++) {
            ull wk[3][3];
#pragma unroll
            for (int dc = 0; dc < 3; dc++)
#pragma unroll
                for (int tp = 0; tp < 3; tp++)
                    wk[dc][tp] = *(const ull*)(w3p + 2 * ((dc * 3 + dhi) * 3 + tp));
#pragma unroll
            for (int p = 0; p < 6; p++) {   // local input plane cq*4 + p
                const float* row = buf + ((cq * 4 + p) * 10 + (hq + dhi)) * 64 + wg * 8;
                float4 m0 = *(const float4*)row;
                float4 m1 = *(const float4*)(row + 4);
                float left  = (wg == 0) ? 0.f : row[-1];
                float right = (wg == 7) ? 0.f : row[8];
                ull E0, E1, E2, E3, E4, O0, O1, O2, O3;
                PK2(E0, left, m0.x);  PK2(E1, m0.y, m0.z);
                PK2(E2, m0.w, m1.x);  PK2(E3, m1.y, m1.z);
                PK2(E4, m1.w, right);
                PK2(O0, m0.x, m0.y);  PK2(O1, m0.z, m0.w);
                PK2(O2, m1.x, m1.y);  PK2(O3, m1.z, m1.w);
#pragma unroll
                for (int dc = 0; dc < 3; dc++) {
                    int cc = p - dc;
                    if (cc < 0 || cc > 3) continue;
                    FMA2(r[cc][0], wk[dc][0], E0); FMA2(r[cc][0], wk[dc][1], O0); FMA2(r[cc][0], wk[dc][2], E1);
                    FMA2(r[cc][1], wk[dc][0], E1); FMA2(r[cc][1], wk[dc][1], O1); FMA2(r[cc][1], wk[dc][2], E2);
                    FMA2(r[cc][2], wk[dc][0], E2); FMA2(r[cc][2], wk[dc][1], O2); FMA2(r[cc][2], wk[dc][2], E3);
                    FMA2(r[cc][3], wk[dc][0], E3); FMA2(r[cc][3], wk[dc][1], O3); FMA2(r[cc][3], wk[dc][2], E4);
                }
            }
        }

        // epilogue for this chunk
        int c0 = quarter * 128 + ch * 16;
#pragma unroll
        for (int cc = 0; cc < 4; cc++) {
            int c = c0 + cq * 4 + cc;
            const float* ctr = buf + ((cq * 4 + cc + 1) * 10 + (hq + 1)) * 64 + wg * 8;
            float4 xi0 = *(const float4*)ctr;
            float4 xi1 = *(const float4*)(ctr + 4);
            uint4 cv = *(const uint4*)(g_cp + ((size_t)(b * 512 + c) * 64 + h) * 64 + wg * 8);
            const __nv_bfloat162* cpp = (const __nv_bfloat162*)&cv;
            float xin[8] = {xi0.x, xi0.y, xi0.z, xi0.w, xi1.x, xi1.y, xi1.z, xi1.w};
            float o[8];
#pragma unroll
            for (int p = 0; p < 4; p++) {
                float lo, hi;
                UPK2(lo, hi, r[cc][p]);
                float2 cf = __bfloat1622float2(cpp[p]);
                o[2 * p]     = lo * (__expf(cf.x) * inv[2 * p])     + xin[2 * p];
                o[2 * p + 1] = hi * (__expf(cf.y) * inv[2 * p + 1]) + xin[2 * p + 1];
            }
            float* op = out + (((size_t)(b * 512 + c) * 64 + h) * 64 + wg * 8);
            *(float4*)(op)     = make_float4(o[0], o[1], o[2], o[3]);
            *(float4*)(op + 4) = make_float4(o[4], o[5], o[6], o[7]);
        }
        __syncthreads();   // buffer reuse guard before next prefetch
    }
}

// ---------------------------------------------------------------------------
extern "C" void kernel_launch(void* const* d_in, const int* in_sizes, int n_in,
                              void* d_out, int out_size) {
    const float* x   = (const float*)d_in[0];
    const float* w_c = (const float*)d_in[1];
    const float* a_c = (const float*)d_in[2];
    const float* w_w = (const float*)d_in[3];
    const float* a_w = (const float*)d_in[4];
    const float* w_h = (const float*)d_in[5];
    const float* a_h = (const float*)d_in[6];
    const float* w3d = (const float*)d_in[7];
    float* out = (float*)d_out;

    cudaFuncSetAttribute(k_gemmE, cudaFuncAttributeMaxDynamicSharedMemorySize, GE_BYTES);
    cudaFuncSetAttribute(k_conv, cudaFuncAttributeMaxDynamicSharedMemorySize, CV_BYTES);

    k_reduce<<<Bn * Cn, 256>>>(x);
    dim3 gridGap(Bn, 2);
    k_gap2<<<gridGap, 256>>>(w_w, a_w, w_h, a_h);
    dim3 gridG(4, 16, Bn);
    k_gemmE<<<gridG, 256, GE_BYTES>>>(w_c, a_c);
    dim3 gridC(8, 4, Bn);
    k_conv<<<gridC, 256, CV_BYTES>>>(x, w3d, out);
}